// round 1
// baseline (speedup 1.0000x reference)
#include <cuda_runtime.h>
#include <math.h>

#define BATCH   16
#define SEQ     17
#define NNODE   256
#define FDIM    64
#define LWIN    16          // (17-2)/1+1
#define BP      256         // BATCH*LWIN
#define N1      512         // MW*NNODE
#define MWW     2
#define OUTD    64
#define NTOT    (BP*N1)     // 131072 rows for BN stats
#define SLOPE   0.01f

// ---------------- scratch (device globals: allocation-free) ----------------
__device__ float g_nf [(size_t)BP*N1*FDIM];   // 33.5 MB
__device__ float g_adj[(size_t)BP*N1*N1];     // 268 MB
__device__ float g_y1 [(size_t)BP*N1*FDIM];   // 33.5 MB
__device__ float g_op [(size_t)BP*N1*OUTD];   // 33.5 MB
__device__ float g_part[2][BP][128];          // per-batch partial sum/sumsq
__device__ float g_coef[2][2][64];            // [which][a|d][channel]

// ---------------- K0: nf = gather(X) @ w_map2^T + b_map2 -------------------
__global__ void k_nf(const float* __restrict__ x, const float* __restrict__ w2,
                     const float* __restrict__ b2) {
    __shared__ float xs[64 * 65];
    __shared__ float ws[64 * 65];
    const int tile  = blockIdx.x;   // 0..7  (64-row tiles of N1=512)
    const int batch = blockIdx.y;   // 0..255
    const int tid   = threadIdx.x;
    const int b = batch / LWIN, l = batch % LWIN;

    for (int e = tid; e < 64 * 64; e += 256) {
        const int rl = e >> 6, k = e & 63;
        const int i = tile * 64 + rl;
        const int m = i >> 8, n = i & 255;          // i = m*256 + n
        xs[rl * 65 + k] = x[(((size_t)(b * SEQ + l + m)) * NNODE + n) * FDIM + k];
        ws[rl * 65 + k] = w2[e];
    }
    __syncthreads();

    const int tr = tid >> 4, tc = tid & 15;         // 16x16 thread grid, 4x4 tiles
    float acc[4][4];
#pragma unroll
    for (int i = 0; i < 4; i++)
#pragma unroll
        for (int j = 0; j < 4; j++) acc[i][j] = b2[tc * 4 + j];

    for (int k = 0; k < 64; k++) {
        float xv[4], wv[4];
#pragma unroll
        for (int i = 0; i < 4; i++) xv[i] = xs[(tr * 4 + i) * 65 + k];
#pragma unroll
        for (int j = 0; j < 4; j++) wv[j] = ws[(tc * 4 + j) * 65 + k];
#pragma unroll
        for (int i = 0; i < 4; i++)
#pragma unroll
            for (int j = 0; j < 4; j++) acc[i][j] += xv[i] * wv[j];
    }
    const size_t base = ((size_t)batch * N1 + tile * 64) * FDIM;
#pragma unroll
    for (int i = 0; i < 4; i++)
#pragma unroll
        for (int j = 0; j < 4; j++)
            g_nf[base + (size_t)(tr * 4 + i) * FDIM + tc * 4 + j] = acc[i][j];
}

// ---------------- BN stats: deterministic 2-stage reduction ----------------
__global__ void k_stats_p1(int which) {
    const float* src = (which == 0) ? g_nf : g_op;
    const int batch = blockIdx.x;
    const int tid = threadIdx.x;
    const int c = tid & 63, rg = tid >> 6;          // 4 row groups x 64 channels
    float s = 0.f, q = 0.f;
    const float* p = src + (size_t)batch * N1 * 64;
    for (int r = rg * 128; r < rg * 128 + 128; r++) {
        float v = p[(size_t)r * 64 + c];
        s += v; q += v * v;
    }
    __shared__ float sm[256], qm[256];
    sm[tid] = s; qm[tid] = q;
    __syncthreads();
    if (tid < 64) {
        g_part[which][batch][tid]      = sm[tid] + sm[tid + 64] + sm[tid + 128] + sm[tid + 192];
        g_part[which][batch][tid + 64] = qm[tid] + qm[tid + 64] + qm[tid + 128] + qm[tid + 192];
    }
}

__global__ void k_stats_p2(const float* __restrict__ w, const float* __restrict__ bb, int which) {
    const int c = threadIdx.x;                      // 64 threads
    float s = 0.f, q = 0.f;
    for (int b2 = 0; b2 < BP; b2++) { s += g_part[which][b2][c]; q += g_part[which][b2][c + 64]; }
    const float mu  = s / (float)NTOT;
    const float var = q / (float)NTOT - mu * mu;    // biased variance
    const float a   = w[c] * rsqrtf(var + 1e-5f);
    g_coef[which][0][c] = a;
    g_coef[which][1][c] = bb[c] - mu * a;
}

// ---------------- K2: adjacency (softmax+eye+mask) and y1 = adj @ xb -------
__global__ void __launch_bounds__(256) k_adj_y1() {
    extern __shared__ float smem[];
    float* nf_s  = smem;                 // 512*65
    float* adj_s = smem + 512 * 65;      // 32*513
    float* srow  = adj_s + 32 * 513;     // 32
    const int tile = blockIdx.x;         // 0..15 (32-row tiles)
    const int batch = blockIdx.y;
    const int tid = threadIdx.x;

    const float* nfg = g_nf + (size_t)batch * N1 * 64;
    for (int e = tid; e < N1 * 64; e += 256)
        nf_s[(e >> 6) * 65 + (e & 63)] = nfg[e];
    __syncthreads();

    const int ty = tid >> 5, tx = tid & 31;   // warp ty owns 4 rows; lanes own strided cols
    float acc[4][16];
#pragma unroll
    for (int i = 0; i < 4; i++)
#pragma unroll
        for (int j = 0; j < 16; j++) acc[i][j] = 0.f;

    const int r0 = tile * 32 + ty * 4;
    for (int k = 0; k < 64; k++) {
        float rv[4], cv[16];
#pragma unroll
        for (int i = 0; i < 4; i++) rv[i] = nf_s[(r0 + i) * 65 + k];
#pragma unroll
        for (int j = 0; j < 16; j++) cv[j] = nf_s[(tx + 32 * j) * 65 + k];
#pragma unroll
        for (int i = 0; i < 4; i++)
#pragma unroll
            for (int j = 0; j < 16; j++) acc[i][j] += rv[i] * cv[j];
    }

#pragma unroll
    for (int i = 0; i < 4; i++) {
        const int r = r0 + i;
        float m = -3.4e38f;
#pragma unroll
        for (int j = 0; j < 16; j++) {
            const int col = tx + 32 * j;
            float v = acc[i][j];
            if (col == r) v -= 1e8f;                       // kill diagonal
            v = v > 0.f ? v : SLOPE * v;                   // leaky_relu
            acc[i][j] = v;
            m = fmaxf(m, v);
        }
#pragma unroll
        for (int o = 16; o > 0; o >>= 1) m = fmaxf(m, __shfl_xor_sync(0xffffffffu, m, o));
        float sum = 0.f;
#pragma unroll
        for (int j = 0; j < 16; j++) { float e = expf(acc[i][j] - m); acc[i][j] = e; sum += e; }
#pragma unroll
        for (int o = 16; o > 0; o >>= 1) sum += __shfl_xor_sync(0xffffffffu, sum, o);
        const float inv = 1.f / sum;
        float s = 0.f;
        const size_t gbase = ((size_t)batch * N1 + r) * N1;
#pragma unroll
        for (int j = 0; j < 16; j++) {
            const int col = tx + 32 * j;
            float v = acc[i][j] * inv;
            if (col == r) v += 1.f;                        // + eye
            if ((r ^ col) & 256) v *= 0.7f;                // decay mask (cross-block)
            adj_s[(ty * 4 + i) * 513 + col] = v;
            g_adj[gbase + col] = v;                        // coalesced: 32 consecutive cols
            s += v;
        }
#pragma unroll
        for (int o = 16; o > 0; o >>= 1) s += __shfl_xor_sync(0xffffffffu, s, o);
        if (tx == 0) srow[ty * 4 + i] = s;
    }
    __syncthreads();

    // y1 = a ⊙ (adj @ nf) + d * rowsum(adj)   (xb never materialized)
    const int tr2 = tid >> 4, tc2 = tid & 15;  // 16 row-pairs x 16 f-quads
    float z[2][4];
#pragma unroll
    for (int rr = 0; rr < 2; rr++)
#pragma unroll
        for (int u = 0; u < 4; u++) z[rr][u] = 0.f;
    for (int k = 0; k < N1; k++) {
        const float a0 = adj_s[(tr2 * 2) * 513 + k];
        const float a1 = adj_s[(tr2 * 2 + 1) * 513 + k];
        float yv[4];
#pragma unroll
        for (int u = 0; u < 4; u++) yv[u] = nf_s[k * 65 + tc2 * 4 + u];
#pragma unroll
        for (int u = 0; u < 4; u++) { z[0][u] += a0 * yv[u]; z[1][u] += a1 * yv[u]; }
    }
#pragma unroll
    for (int rr = 0; rr < 2; rr++) {
        const int rl = tr2 * 2 + rr;
        const int r = tile * 32 + rl;
        const float sr = srow[rl];
#pragma unroll
        for (int u = 0; u < 4; u++) {
            const int f = tc2 * 4 + u;
            g_y1[((size_t)batch * N1 + r) * 64 + f] = g_coef[0][0][f] * z[rr][u] + g_coef[0][1][f] * sr;
        }
    }
}

// ---------------- K3: y2 = adj @ y1 ; outpre = y1@th0^T + y2@th1^T + b -----
__global__ void __launch_bounds__(256) k_y2_out(const float* __restrict__ th0w,
                                                const float* __restrict__ th0b,
                                                const float* __restrict__ th1w,
                                                const float* __restrict__ th1b) {
    extern __shared__ float smem[];
    float* y1_s = smem;                     // 512*65
    float* th0s = y1_s + 512 * 65;          // 64*65 (padded: kills bank conflict)
    float* th1s = th0s + 64 * 65;           // 64*65
    float* adjc = th1s + 64 * 65;           // 32*65
    float* y2_s = adjc + 32 * 65;           // 32*65
    const int tile = blockIdx.x, batch = blockIdx.y, tid = threadIdx.x;

    const float* y1g = g_y1 + (size_t)batch * N1 * 64;
    for (int e = tid; e < N1 * 64; e += 256) y1_s[(e >> 6) * 65 + (e & 63)] = y1g[e];
    for (int e = tid; e < 64 * 64; e += 256) {
        th0s[(e >> 6) * 65 + (e & 63)] = th0w[e];
        th1s[(e >> 6) * 65 + (e & 63)] = th1w[e];
    }
    __syncthreads();

    const int tr2 = tid >> 4, tc2 = tid & 15;
    float z[2][4];
#pragma unroll
    for (int rr = 0; rr < 2; rr++)
#pragma unroll
        for (int u = 0; u < 4; u++) z[rr][u] = 0.f;

    const float* adjg = g_adj + ((size_t)batch * N1 + tile * 32) * N1;
    for (int ch = 0; ch < 8; ch++) {
        for (int e = tid; e < 32 * 64; e += 256)
            adjc[(e >> 6) * 65 + (e & 63)] = adjg[(size_t)(e >> 6) * N1 + ch * 64 + (e & 63)];
        __syncthreads();
        for (int kk = 0; kk < 64; kk++) {
            const int k = ch * 64 + kk;
            const float a0 = adjc[(tr2 * 2) * 65 + kk];
            const float a1 = adjc[(tr2 * 2 + 1) * 65 + kk];
            float yv[4];
#pragma unroll
            for (int u = 0; u < 4; u++) yv[u] = y1_s[k * 65 + tc2 * 4 + u];
#pragma unroll
            for (int u = 0; u < 4; u++) { z[0][u] += a0 * yv[u]; z[1][u] += a1 * yv[u]; }
        }
        __syncthreads();
    }

#pragma unroll
    for (int rr = 0; rr < 2; rr++)
#pragma unroll
        for (int u = 0; u < 4; u++) y2_s[(tr2 * 2 + rr) * 65 + tc2 * 4 + u] = z[rr][u];
    __syncthreads();

    float o[2][4];
#pragma unroll
    for (int rr = 0; rr < 2; rr++)
#pragma unroll
        for (int u = 0; u < 4; u++) o[rr][u] = th0b[tc2 * 4 + u] + th1b[tc2 * 4 + u];

    for (int g = 0; g < 64; g++) {
        const float y1v0 = y1_s[(tile * 32 + tr2 * 2) * 65 + g];
        const float y1v1 = y1_s[(tile * 32 + tr2 * 2 + 1) * 65 + g];
        const float y2v0 = y2_s[(tr2 * 2) * 65 + g];
        const float y2v1 = y2_s[(tr2 * 2 + 1) * 65 + g];
#pragma unroll
        for (int u = 0; u < 4; u++) {
            const float w0 = th0s[(tc2 * 4 + u) * 65 + g];
            const float w1 = th1s[(tc2 * 4 + u) * 65 + g];
            o[0][u] += y1v0 * w0 + y2v0 * w1;
            o[1][u] += y1v1 * w0 + y2v1 * w1;
        }
    }
#pragma unroll
    for (int rr = 0; rr < 2; rr++)
#pragma unroll
        for (int u = 0; u < 4; u++)
            g_op[((size_t)batch * N1 + tile * 32 + tr2 * 2 + rr) * 64 + tc2 * 4 + u] = o[rr][u];
}

// ---------------- K4: BN1 affine + leaky + mean-pool to [16,256,64] --------
__global__ void k_final(float* __restrict__ out) {
    const int idx = blockIdx.x * 256 + threadIdx.x;     // 262144 outputs
    const int c = idx & 63;
    const int n = (idx >> 6) & 255;
    const int b = idx >> 14;
    const float a = g_coef[1][0][c], d = g_coef[1][1][c];
    float s = 0.f;
#pragma unroll 2
    for (int l = 0; l < LWIN; l++)
#pragma unroll
        for (int m = 0; m < MWW; m++) {
            float v = g_op[(((size_t)(b * LWIN + l)) * N1 + m * NNODE + n) * 64 + c];
            v = a * v + d;
            s += (v > 0.f) ? v : SLOPE * v;
        }
    out[idx] = s * (1.f / 32.f);
}

// ---------------- launch ---------------------------------------------------
extern "C" void kernel_launch(void* const* d_in, const int* in_sizes, int n_in,
                              void* d_out, int out_size) {
    const float* x    = (const float*)d_in[0];
    const float* w2   = (const float*)d_in[1];
    const float* b2   = (const float*)d_in[2];
    const float* bn0w = (const float*)d_in[3];
    const float* bn0b = (const float*)d_in[4];
    const float* th0w = (const float*)d_in[5];
    const float* th0b = (const float*)d_in[6];
    const float* th1w = (const float*)d_in[7];
    const float* th1b = (const float*)d_in[8];
    const float* bn1w = (const float*)d_in[9];
    const float* bn1b = (const float*)d_in[10];
    float* out = (float*)d_out;

    const int SMEM_A = (512 * 65 + 32 * 513 + 32) * 4;               // 198912 B
    const int SMEM_B = (512 * 65 + 64 * 65 * 2 + 32 * 65 * 2) * 4;   // 183040 B
    cudaFuncSetAttribute(k_adj_y1, cudaFuncAttributeMaxDynamicSharedMemorySize, SMEM_A);
    cudaFuncSetAttribute(k_y2_out, cudaFuncAttributeMaxDynamicSharedMemorySize, SMEM_B);

    k_nf<<<dim3(8, BP), 256>>>(x, w2, b2);
    k_stats_p1<<<BP, 256>>>(0);
    k_stats_p2<<<1, 64>>>(bn0w, bn0b, 0);
    k_adj_y1<<<dim3(16, BP), 256, SMEM_A>>>();
    k_y2_out<<<dim3(16, BP), 256, SMEM_B>>>(th0w, th0b, th1w, th1b);
    k_stats_p1<<<BP, 256>>>(1);
    k_stats_p2<<<1, 64>>>(bn1w, bn1b, 1);
    k_final<<<(BATCH * NNODE * OUTD) / 256, 256>>>(out);
}

// round 2
// speedup vs baseline: 1.8025x; 1.8025x over previous
#include <cuda_runtime.h>
#include <math.h>

#define BATCH   16
#define SEQ     17
#define NNODE   256
#define FDIM    64
#define LWIN    16          // (17-2)/1+1
#define BP      256         // BATCH*LWIN
#define N1      512         // MW*NNODE
#define MWW     2
#define OUTD    64
#define NTOT    (BP*N1)
#define SLOPE   0.01f

// ---------------- scratch (device globals: allocation-free) ----------------
__device__ float g_nf [(size_t)BP*N1*FDIM];   // fp32 (exact, for BN stats)
__device__ float g_adj[(size_t)BP*N1*N1];     // tf32-rounded values in fp32
__device__ float g_y1 [(size_t)BP*N1*FDIM];
__device__ float g_op [(size_t)BP*N1*OUTD];
__device__ float g_part[2][BP][128];
__device__ float g_coef[2][2][64];

// ---------------- helpers ---------------------------------------------------
__device__ __forceinline__ unsigned f2tf(float x) {
    unsigned u; asm("cvt.rna.tf32.f32 %0, %1;" : "=r"(u) : "f"(x)); return u;
}
__device__ __forceinline__ void mma_tf32(float c[4], unsigned a0, unsigned a1,
                                         unsigned a2, unsigned a3,
                                         unsigned b0, unsigned b1) {
    asm volatile(
        "mma.sync.aligned.m16n8k8.row.col.f32.tf32.tf32.f32 "
        "{%0,%1,%2,%3},{%4,%5,%6,%7},{%8,%9},{%0,%1,%2,%3};"
        : "+f"(c[0]), "+f"(c[1]), "+f"(c[2]), "+f"(c[3])
        : "r"(a0), "r"(a1), "r"(a2), "r"(a3), "r"(b0), "r"(b1));
}
__device__ __forceinline__ unsigned bits(float x) { return __float_as_uint(x); }

// ---------------- K0: nf = gather(X) @ w_map2^T + b_map2 -------------------
__global__ void k_nf(const float* __restrict__ x, const float* __restrict__ w2,
                     const float* __restrict__ b2) {
    __shared__ float xs[64 * 65];
    __shared__ float ws[64 * 65];
    const int tile  = blockIdx.x;   // 0..7
    const int batch = blockIdx.y;   // 0..255
    const int tid   = threadIdx.x;
    const int b = batch / LWIN, l = batch % LWIN;

    for (int e = tid; e < 64 * 64; e += 256) {
        const int rl = e >> 6, k = e & 63;
        const int i = tile * 64 + rl;
        const int m = i >> 8, n = i & 255;
        xs[rl * 65 + k] = x[(((size_t)(b * SEQ + l + m)) * NNODE + n) * FDIM + k];
        ws[rl * 65 + k] = w2[e];
    }
    __syncthreads();

    const int tr = tid >> 4, tc = tid & 15;
    float acc[4][4];
#pragma unroll
    for (int i = 0; i < 4; i++)
#pragma unroll
        for (int j = 0; j < 4; j++) acc[i][j] = b2[tc * 4 + j];

    for (int k = 0; k < 64; k++) {
        float xv[4], wv[4];
#pragma unroll
        for (int i = 0; i < 4; i++) xv[i] = xs[(tr * 4 + i) * 65 + k];
#pragma unroll
        for (int j = 0; j < 4; j++) wv[j] = ws[(tc * 4 + j) * 65 + k];
#pragma unroll
        for (int i = 0; i < 4; i++)
#pragma unroll
            for (int j = 0; j < 4; j++) acc[i][j] += xv[i] * wv[j];
    }
    const size_t base = ((size_t)batch * N1 + tile * 64) * FDIM;
#pragma unroll
    for (int i = 0; i < 4; i++)
#pragma unroll
        for (int j = 0; j < 4; j++)
            g_nf[base + (size_t)(tr * 4 + i) * FDIM + tc * 4 + j] = acc[i][j];
}

// ---------------- BN stats: deterministic 2-stage reduction ----------------
__global__ void k_stats_p1(int which) {
    const float* src = (which == 0) ? g_nf : g_op;
    const int batch = blockIdx.x;
    const int tid = threadIdx.x;
    const int c = tid & 63, rg = tid >> 6;
    float s = 0.f, q = 0.f;
    const float* p = src + (size_t)batch * N1 * 64;
    for (int r = rg * 128; r < rg * 128 + 128; r++) {
        float v = p[(size_t)r * 64 + c];
        s += v; q += v * v;
    }
    __shared__ float sm[256], qm[256];
    sm[tid] = s; qm[tid] = q;
    __syncthreads();
    if (tid < 64) {
        g_part[which][batch][tid]      = sm[tid] + sm[tid + 64] + sm[tid + 128] + sm[tid + 192];
        g_part[which][batch][tid + 64] = qm[tid] + qm[tid + 64] + qm[tid + 128] + qm[tid + 192];
    }
}

__global__ void k_stats_p2(const float* __restrict__ w, const float* __restrict__ bb, int which) {
    const int c = threadIdx.x;
    float s = 0.f, q = 0.f;
    for (int b2 = 0; b2 < BP; b2++) { s += g_part[which][b2][c]; q += g_part[which][b2][c + 64]; }
    const float mu  = s / (float)NTOT;
    const float var = q / (float)NTOT - mu * mu;
    const float a   = w[c] * rsqrtf(var + 1e-5f);
    g_coef[which][0][c] = a;
    g_coef[which][1][c] = bb[c] - mu * a;
}

// ---------------- K2: scores -> softmax adj -> y1 = BN trick (tf32 MMA) ----
// block: 256 thr (8 warps), grid (16 row-tiles of 32, 256 batches)
// smem floats: nf_s[512*68] | adj_s[32*516] | redm[32*4] | reds[32*4] | srow[32] | y1st[32*68]
__global__ void __launch_bounds__(256) k_adj_y1() {
    extern __shared__ float sm[];
    float* nf_s  = sm;            // 34816
    float* adj_s = sm + 34816;    // 16512
    float* redm  = sm + 51328;    // 128
    float* reds  = sm + 51456;    // 128
    float* srow  = sm + 51584;    // 32
    float* y1st  = sm + 51616;    // 2176
    const int tile = blockIdx.x, batch = blockIdx.y, tid = threadIdx.x;
    const int w = tid >> 5, lane = tid & 31;
    const int band = w >> 2, colg = w & 3;
    const int lq = lane >> 2, lr = lane & 3;

    const float* nfg = g_nf + (size_t)batch * N1 * FDIM;
    for (int e = tid; e < N1 * FDIM; e += 256)
        nf_s[(e >> 6) * 68 + (e & 63)] = __uint_as_float(f2tf(nfg[e]));
    __syncthreads();

    // ---- scores: S = nf @ nf^T  (warp: 16 rows x 128 cols) ----
    float acc[16][4];
#pragma unroll
    for (int t = 0; t < 16; t++) { acc[t][0] = acc[t][1] = acc[t][2] = acc[t][3] = 0.f; }
    const int arow = tile * 32 + band * 16 + lq;
#pragma unroll 2
    for (int ks = 0; ks < 8; ks++) {
        const int k0 = ks * 8 + lr;
        unsigned a0 = bits(nf_s[arow * 68 + k0]);
        unsigned a1 = bits(nf_s[(arow + 8) * 68 + k0]);
        unsigned a2 = bits(nf_s[arow * 68 + k0 + 4]);
        unsigned a3 = bits(nf_s[(arow + 8) * 68 + k0 + 4]);
#pragma unroll
        for (int t = 0; t < 16; t++) {
            const int bn = colg * 128 + t * 8 + lq;
            unsigned b0 = bits(nf_s[bn * 68 + k0]);
            unsigned b1 = bits(nf_s[bn * 68 + k0 + 4]);
            mma_tf32(acc[t], a0, a1, a2, a3, b0, b1);
        }
    }

    // ---- masked leaky + row max ----
    const int rg0 = arow, rg1 = arow + 8;        // global node rows (0..511)
    const int rl0 = band * 16 + lq, rl1 = rl0 + 8;
    float m0 = -1e30f, m1 = -1e30f;
#pragma unroll
    for (int t = 0; t < 16; t++) {
        const int cb = colg * 128 + t * 8 + lr * 2;
#pragma unroll
        for (int j = 0; j < 2; j++) {
            const int col = cb + j;
            float v = acc[t][j];
            if (col == rg0) v -= 1e8f;
            v = v > 0.f ? v : SLOPE * v;
            acc[t][j] = v; m0 = fmaxf(m0, v);
            float u = acc[t][2 + j];
            if (col == rg1) u -= 1e8f;
            u = u > 0.f ? u : SLOPE * u;
            acc[t][2 + j] = u; m1 = fmaxf(m1, u);
        }
    }
    m0 = fmaxf(m0, __shfl_xor_sync(~0u, m0, 1)); m0 = fmaxf(m0, __shfl_xor_sync(~0u, m0, 2));
    m1 = fmaxf(m1, __shfl_xor_sync(~0u, m1, 1)); m1 = fmaxf(m1, __shfl_xor_sync(~0u, m1, 2));
    if (lr == 0) { redm[rl0 * 4 + colg] = m0; redm[rl1 * 4 + colg] = m1; }
    __syncthreads();
    m0 = fmaxf(fmaxf(redm[rl0 * 4 + 0], redm[rl0 * 4 + 1]), fmaxf(redm[rl0 * 4 + 2], redm[rl0 * 4 + 3]));
    m1 = fmaxf(fmaxf(redm[rl1 * 4 + 0], redm[rl1 * 4 + 1]), fmaxf(redm[rl1 * 4 + 2], redm[rl1 * 4 + 3]));

    // ---- exp + partial sums (each warp's 128 cols are entirely lo or hi) ----
    float s0 = 0.f, s1 = 0.f;
#pragma unroll
    for (int t = 0; t < 16; t++) {
#pragma unroll
        for (int j = 0; j < 2; j++) {
            float e0 = __expf(acc[t][j] - m0);     acc[t][j] = e0;     s0 += e0;
            float e1 = __expf(acc[t][2 + j] - m1); acc[t][2 + j] = e1; s1 += e1;
        }
    }
    s0 += __shfl_xor_sync(~0u, s0, 1); s0 += __shfl_xor_sync(~0u, s0, 2);
    s1 += __shfl_xor_sync(~0u, s1, 1); s1 += __shfl_xor_sync(~0u, s1, 2);
    if (lr == 0) { reds[rl0 * 4 + colg] = s0; reds[rl1 * 4 + colg] = s1; }
    __syncthreads();
    const float lo0 = reds[rl0 * 4] + reds[rl0 * 4 + 1], hi0 = reds[rl0 * 4 + 2] + reds[rl0 * 4 + 3];
    const float lo1 = reds[rl1 * 4] + reds[rl1 * 4 + 1], hi1 = reds[rl1 * 4 + 2] + reds[rl1 * 4 + 3];
    const float inv0 = 1.f / (lo0 + hi0), inv1 = 1.f / (lo1 + hi1);
    const bool rlo = (tile < 8);   // row block (lo/hi) is uniform per CTA
    if (lr == 0) {
        srow[rl0] = (rlo ? lo0 + 0.7f * hi0 : 0.7f * lo0 + hi0) * inv0 + 1.f;
        srow[rl1] = (rlo ? lo1 + 0.7f * hi1 : 0.7f * lo1 + hi1) * inv1 + 1.f;
    }
    const float msk = (((colg >= 2) ? 1 : 0) != (rlo ? 0 : 1)) ? 0.7f : 1.0f;

    // ---- normalize, +eye, mask; store tf32 adj tile to smem ----
#pragma unroll
    for (int t = 0; t < 16; t++) {
        const int cb = colg * 128 + t * 8 + lr * 2;
#pragma unroll
        for (int j = 0; j < 2; j++) {
            const int col = cb + j;
            float v = acc[t][j] * inv0;     if (col == rg0) v += 1.f; v *= msk;
            adj_s[rl0 * 516 + col] = __uint_as_float(f2tf(v));
            float u = acc[t][2 + j] * inv1; if (col == rg1) u += 1.f; u *= msk;
            adj_s[rl1 * 516 + col] = __uint_as_float(f2tf(u));
        }
    }
    __syncthreads();

    // ---- coalesced adj tile -> global ----
    {
        const size_t gbase = ((size_t)batch * N1 + tile * 32) * N1;
        for (int e = tid; e < 32 * 128; e += 256) {
            const int r = e >> 7, c4 = e & 127;
            float4 v = *(const float4*)(adj_s + r * 516 + c4 * 4);
            *(float4*)(g_adj + gbase + (size_t)r * N1 + c4 * 4) = v;
        }
    }

    // ---- y1 = a ⊙ (adj @ nf) + d * rowsum   (tf32 MMA, K=512) ----
    float ya[2][4];
#pragma unroll
    for (int t = 0; t < 2; t++) { ya[t][0] = ya[t][1] = ya[t][2] = ya[t][3] = 0.f; }
#pragma unroll 4
    for (int ks = 0; ks < 64; ks++) {
        const int k0 = ks * 8 + lr;
        unsigned a0 = bits(adj_s[rl0 * 516 + k0]);
        unsigned a1 = bits(adj_s[rl1 * 516 + k0]);
        unsigned a2 = bits(adj_s[rl0 * 516 + k0 + 4]);
        unsigned a3 = bits(adj_s[rl1 * 516 + k0 + 4]);
#pragma unroll
        for (int t = 0; t < 2; t++) {
            const int fn = colg * 16 + t * 8 + lq;
            unsigned b0 = bits(nf_s[(k0)     * 68 + fn]);
            unsigned b1 = bits(nf_s[(k0 + 4) * 68 + fn]);
            mma_tf32(ya[t], a0, a1, a2, a3, b0, b1);
        }
    }
    const float sr0 = srow[rl0], sr1 = srow[rl1];
#pragma unroll
    for (int t = 0; t < 2; t++) {
#pragma unroll
        for (int j = 0; j < 2; j++) {
            const int f = colg * 16 + t * 8 + lr * 2 + j;
            const float a = g_coef[0][0][f], d = g_coef[0][1][f];
            y1st[rl0 * 68 + f] = a * ya[t][j]     + d * sr0;
            y1st[rl1 * 68 + f] = a * ya[t][2 + j] + d * sr1;
        }
    }
    __syncthreads();
    for (int e = tid; e < 32 * 64; e += 256) {
        const int r = e >> 6, f = e & 63;
        g_y1[((size_t)batch * N1 + tile * 32 + r) * 64 + f] = y1st[r * 68 + f];
    }
}

// ---------------- K3: y2 = adj @ y1 ; out = y1@th0^T + y2@th1^T + b --------
// smem floats: y1_s[512*68] | adjc[32*132] | th0s[64*68] | th1s[64*68] | y2s[32*68] | opst[32*68]
__global__ void __launch_bounds__(256) k_y2_out(const float* __restrict__ th0w,
                                                const float* __restrict__ th0b,
                                                const float* __restrict__ th1w,
                                                const float* __restrict__ th1b) {
    extern __shared__ float sm[];
    float* y1_s = sm;             // 34816
    float* adjc = sm + 34816;     // 4224
    float* th0s = sm + 39040;     // 4352
    float* th1s = sm + 43392;     // 4352
    float* y2s  = sm + 47744;     // 2176
    float* opst = sm + 49920;     // 2176
    const int tile = blockIdx.x, batch = blockIdx.y, tid = threadIdx.x;
    const int w = tid >> 5, lane = tid & 31;
    const int band = w >> 2, colg = w & 3;
    const int lq = lane >> 2, lr = lane & 3;
    const int rl0 = band * 16 + lq, rl1 = rl0 + 8;

    const float* y1g = g_y1 + (size_t)batch * N1 * 64;
    for (int e = tid; e < N1 * 64; e += 256)
        y1_s[(e >> 6) * 68 + (e & 63)] = __uint_as_float(f2tf(y1g[e]));
    for (int e = tid; e < 64 * 64; e += 256) {
        th0s[(e >> 6) * 68 + (e & 63)] = __uint_as_float(f2tf(th0w[e]));
        th1s[(e >> 6) * 68 + (e & 63)] = __uint_as_float(f2tf(th1w[e]));
    }
    __syncthreads();

    // ---- y2 = adj @ y1 (stream adj in 32x128 chunks) ----
    float ya[2][4];
#pragma unroll
    for (int t = 0; t < 2; t++) { ya[t][0] = ya[t][1] = ya[t][2] = ya[t][3] = 0.f; }
    for (int ch = 0; ch < 4; ch++) {
        for (int e = tid; e < 32 * 32; e += 256) {
            const int r = e >> 5, c4 = e & 31;
            *(float4*)(adjc + r * 132 + c4 * 4) =
                *(const float4*)(g_adj + ((size_t)batch * N1 + tile * 32 + r) * N1 + ch * 128 + c4 * 4);
        }
        __syncthreads();
#pragma unroll 4
        for (int ks = 0; ks < 16; ks++) {
            const int k0 = ks * 8 + lr;
            unsigned a0 = bits(adjc[rl0 * 132 + k0]);
            unsigned a1 = bits(adjc[rl1 * 132 + k0]);
            unsigned a2 = bits(adjc[rl0 * 132 + k0 + 4]);
            unsigned a3 = bits(adjc[rl1 * 132 + k0 + 4]);
            const int kg = ch * 128 + k0;
#pragma unroll
            for (int t = 0; t < 2; t++) {
                const int fn = colg * 16 + t * 8 + lq;
                unsigned b0 = bits(y1_s[(kg)     * 68 + fn]);
                unsigned b1 = bits(y1_s[(kg + 4) * 68 + fn]);
                mma_tf32(ya[t], a0, a1, a2, a3, b0, b1);
            }
        }
        __syncthreads();
    }
    // stage y2 (tf32-rounded) for use as MMA A operand
#pragma unroll
    for (int t = 0; t < 2; t++) {
#pragma unroll
        for (int j = 0; j < 2; j++) {
            const int f = colg * 16 + t * 8 + lr * 2 + j;
            y2s[rl0 * 68 + f] = __uint_as_float(f2tf(ya[t][j]));
            y2s[rl1 * 68 + f] = __uint_as_float(f2tf(ya[t][2 + j]));
        }
    }
    __syncthreads();

    // ---- out = y1 @ th0^T + y2 @ th1^T + (b0 + b1) ----
    float oa[2][4];
#pragma unroll
    for (int t = 0; t < 2; t++) {
        const int o0 = colg * 16 + t * 8 + lr * 2;
        const float bsum0 = th0b[o0] + th1b[o0];
        const float bsum1 = th0b[o0 + 1] + th1b[o0 + 1];
        oa[t][0] = bsum0; oa[t][1] = bsum1; oa[t][2] = bsum0; oa[t][3] = bsum1;
    }
    const int yrow0 = tile * 32 + rl0, yrow1 = tile * 32 + rl1;
#pragma unroll
    for (int ks = 0; ks < 8; ks++) {
        const int k0 = ks * 8 + lr;
        unsigned a0 = bits(y1_s[yrow0 * 68 + k0]);
        unsigned a1 = bits(y1_s[yrow1 * 68 + k0]);
        unsigned a2 = bits(y1_s[yrow0 * 68 + k0 + 4]);
        unsigned a3 = bits(y1_s[yrow1 * 68 + k0 + 4]);
        unsigned c0 = bits(y2s[rl0 * 68 + k0]);
        unsigned c1 = bits(y2s[rl1 * 68 + k0]);
        unsigned c2 = bits(y2s[rl0 * 68 + k0 + 4]);
        unsigned c3 = bits(y2s[rl1 * 68 + k0 + 4]);
#pragma unroll
        for (int t = 0; t < 2; t++) {
            const int fn = colg * 16 + t * 8 + lq;
            unsigned b0 = bits(th0s[fn * 68 + k0]);
            unsigned b1 = bits(th0s[fn * 68 + k0 + 4]);
            mma_tf32(oa[t], a0, a1, a2, a3, b0, b1);
            unsigned d0 = bits(th1s[fn * 68 + k0]);
            unsigned d1 = bits(th1s[fn * 68 + k0 + 4]);
            mma_tf32(oa[t], c0, c1, c2, c3, d0, d1);
        }
    }
#pragma unroll
    for (int t = 0; t < 2; t++) {
#pragma unroll
        for (int j = 0; j < 2; j++) {
            const int f = colg * 16 + t * 8 + lr * 2 + j;
            opst[rl0 * 68 + f] = oa[t][j];
            opst[rl1 * 68 + f] = oa[t][2 + j];
        }
    }
    __syncthreads();
    for (int e = tid; e < 32 * 64; e += 256) {
        const int r = e >> 6, f = e & 63;
        g_op[((size_t)batch * N1 + tile * 32 + r) * 64 + f] = opst[r * 68 + f];
    }
}

// ---------------- K4: BN1 affine + leaky + mean-pool to [16,256,64] --------
__global__ void k_final(float* __restrict__ out) {
    const int idx = blockIdx.x * 256 + threadIdx.x;
    const int c = idx & 63;
    const int n = (idx >> 6) & 255;
    const int b = idx >> 14;
    const float a = g_coef[1][0][c], d = g_coef[1][1][c];
    float s = 0.f;
#pragma unroll 2
    for (int l = 0; l < LWIN; l++)
#pragma unroll
        for (int m = 0; m < MWW; m++) {
            float v = g_op[(((size_t)(b * LWIN + l)) * N1 + m * NNODE + n) * 64 + c];
            v = a * v + d;
            s += (v > 0.f) ? v : SLOPE * v;
        }
    out[idx] = s * (1.f / 32.f);
}

// ---------------- launch ---------------------------------------------------
extern "C" void kernel_launch(void* const* d_in, const int* in_sizes, int n_in,
                              void* d_out, int out_size) {
    const float* x    = (const float*)d_in[0];
    const float* w2   = (const float*)d_in[1];
    const float* b2   = (const float*)d_in[2];
    const float* bn0w = (const float*)d_in[3];
    const float* bn0b = (const float*)d_in[4];
    const float* th0w = (const float*)d_in[5];
    const float* th0b = (const float*)d_in[6];
    const float* th1w = (const float*)d_in[7];
    const float* th1b = (const float*)d_in[8];
    const float* bn1w = (const float*)d_in[9];
    const float* bn1b = (const float*)d_in[10];
    float* out = (float*)d_out;

    const int SMEM_A = 53792 * 4;   // 215168 B
    const int SMEM_B = 52096 * 4;   // 208384 B
    cudaFuncSetAttribute(k_adj_y1, cudaFuncAttributeMaxDynamicSharedMemorySize, SMEM_A);
    cudaFuncSetAttribute(k_y2_out, cudaFuncAttributeMaxDynamicSharedMemorySize, SMEM_B);

    k_nf<<<dim3(8, BP), 256>>>(x, w2, b2);
    k_stats_p1<<<BP, 256>>>(0);
    k_stats_p2<<<1, 64>>>(bn0w, bn0b, 0);
    k_adj_y1<<<dim3(16, BP), 256, SMEM_A>>>();
    k_y2_out<<<dim3(16, BP), 256, SMEM_B>>>(th0w, th0b, th1w, th1b);
    k_stats_p1<<<BP, 256>>>(1);
    k_stats_p2<<<1, 64>>>(bn1w, bn1b, 1);
    k_final<<<(BATCH * NNODE * OUTD) / 256, 256>>>(out);
}

// round 4
// speedup vs baseline: 4.0289x; 2.2351x over previous
#include <cuda_runtime.h>
#include <math.h>
#include <stdint.h>

#define BATCH   16
#define SEQ     17
#define NNODE   256
#define FDIM    64
#define LWIN    16
#define BP      256         // BATCH*LWIN
#define N1      512
#define OUTD    64
#define NTOT    (BP*N1)
#define SLOPE   0.01f

// ---------------- scratch ----------------------------------------------------
__device__ float g_nf [(size_t)BP*N1*FDIM];   // tf32-rounded
__device__ float g_z1 [(size_t)BP*N1*FDIM];   // exact fp32
__device__ float g_w1 [(size_t)BP*N1*FDIM];   // tf32-rounded
__device__ float g_adj[(size_t)BP*N1*N1];     // tf32-rounded
__device__ float g_t  [(size_t)BP*N1*FDIM];   // tf32-rounded
__device__ float g_op [(size_t)BP*N1*OUTD];   // exact fp32
__device__ float g_part[2][BP][128];
__device__ float g_coef[2][2][64];

// ---------------- helpers ----------------------------------------------------
__device__ __forceinline__ float tfr(float x) {
    unsigned u; asm("cvt.rna.tf32.f32 %0, %1;" : "=r"(u) : "f"(x));
    return __uint_as_float(u);
}
__device__ __forceinline__ unsigned bits(float x) { return __float_as_uint(x); }
__device__ __forceinline__ void mma_tf32(float c[4], unsigned a0, unsigned a1,
                                         unsigned a2, unsigned a3,
                                         unsigned b0, unsigned b1) {
    asm volatile(
        "mma.sync.aligned.m16n8k8.row.col.f32.tf32.tf32.f32 "
        "{%0,%1,%2,%3},{%4,%5,%6,%7},{%8,%9},{%0,%1,%2,%3};"
        : "+f"(c[0]), "+f"(c[1]), "+f"(c[2]), "+f"(c[3])
        : "r"(a0), "r"(a1), "r"(a2), "r"(a3), "r"(b0), "r"(b1));
}
__device__ __forceinline__ uint32_t sptr(const void* p) {
    return (uint32_t)__cvta_generic_to_shared(p);
}
__device__ __forceinline__ void cp16(uint32_t d, const float* s) {
    asm volatile("cp.async.cg.shared.global [%0],[%1],16;" :: "r"(d), "l"(s));
}
#define CP_COMMIT asm volatile("cp.async.commit_group;")
#define CP_WAIT0  asm volatile("cp.async.wait_group 0;")
#define CP_WAIT1  asm volatile("cp.async.wait_group 1;")

// ldmatrix.x4 on fp32 data (b16 rows of 16B = 4 floats): lane L of matrix m gets
// T[row0 + (m&1)*8 + L/4][k0 + (m>>1)*4 + L%4]  -> exactly the tf32 A-fragment.
__device__ __forceinline__ void ldsm4(unsigned& r0, unsigned& r1, unsigned& r2, unsigned& r3,
                                      const float* base, int row0, int k0, int stride) {
    const int lane = threadIdx.x & 31;
    uint32_t a = sptr(base + (row0 + (lane & 15)) * stride + k0 + ((lane >> 4) << 2));
    asm volatile("ldmatrix.sync.aligned.m8n8.x4.shared.b16 {%0,%1,%2,%3},[%4];"
                 : "=r"(r0), "=r"(r1), "=r"(r2), "=r"(r3) : "r"(a));
}

// ---------------- K1: nf = gather(X) @ w2^T + b2  (tf32 MMA) ----------------
__global__ void __launch_bounds__(256) k_nf(const float* __restrict__ x,
                                            const float* __restrict__ w2,
                                            const float* __restrict__ b2) {
    __shared__ float xs[64 * 68];
    __shared__ float ws[64 * 68];
    const int tile = blockIdx.x, batch = blockIdx.y, tid = threadIdx.x;
    const int b = batch / LWIN, l = batch % LWIN;

    // full 64x64 fills: 64 rows x 16 chunks of 16B
    for (int e = tid; e < 1024; e += 256) {
        const int row = e >> 4, c4 = e & 15;
        const int r = tile * 64 + row, m = r >> 8, n = r & 255;
        cp16(sptr(xs + row * 68 + c4 * 4),
             x + (((size_t)(b * SEQ + l + m) * NNODE + n) * FDIM) + c4 * 4);
        cp16(sptr(ws + row * 68 + c4 * 4), w2 + row * 64 + c4 * 4);
    }
    CP_COMMIT; CP_WAIT0;
    __syncthreads();
    for (int e = tid; e < 64 * 68; e += 256) { xs[e] = tfr(xs[e]); ws[e] = tfr(ws[e]); }
    __syncthreads();

    const int w = tid >> 5, lane = tid & 31;
    const int band = w >> 1, colg = w & 1;
    const int lq = lane >> 2, lr = lane & 3;
    float acc[4][4];
#pragma unroll
    for (int t = 0; t < 4; t++) { acc[t][0] = acc[t][1] = acc[t][2] = acc[t][3] = 0.f; }
    const int r0 = band * 16;
#pragma unroll
    for (int ks = 0; ks < 8; ks++) {
        const int k0 = ks * 8;
        unsigned a0, a1, a2, a3; ldsm4(a0, a1, a2, a3, xs, r0, k0, 68);
#pragma unroll
        for (int tt = 0; tt < 2; tt++) {
            unsigned q0, q1, q2, q3; ldsm4(q0, q1, q2, q3, ws, colg * 32 + tt * 16, k0, 68);
            mma_tf32(acc[tt * 2],     a0, a1, a2, a3, q0, q2);
            mma_tf32(acc[tt * 2 + 1], a0, a1, a2, a3, q1, q3);
        }
    }
    const size_t ob = ((size_t)batch * N1 + tile * 64 + r0 + lq) * 64;
#pragma unroll
    for (int t = 0; t < 4; t++) {
        const int c = colg * 32 + t * 8 + lr * 2;
        const float bb0 = __ldg(b2 + c), bb1 = __ldg(b2 + c + 1);
        float2 v0 = make_float2(tfr(acc[t][0] + bb0), tfr(acc[t][1] + bb1));
        float2 v1 = make_float2(tfr(acc[t][2] + bb0), tfr(acc[t][3] + bb1));
        *(float2*)(g_nf + ob + c) = v0;
        *(float2*)(g_nf + ob + (size_t)8 * 64 + c) = v1;
    }
}

// ---------------- BN stats ---------------------------------------------------
__global__ void k_stats_p1(int which) {
    const float* src = (which == 0) ? g_nf : g_op;
    const int batch = blockIdx.x, tid = threadIdx.x;
    const int c = tid & 63, rg = tid >> 6;
    float s = 0.f, q = 0.f;
    const float* p = src + (size_t)batch * N1 * 64;
    for (int r = rg * 128; r < rg * 128 + 128; r++) {
        float v = p[(size_t)r * 64 + c];
        s += v; q += v * v;
    }
    __shared__ float sm[256], qm[256];
    sm[tid] = s; qm[tid] = q;
    __syncthreads();
    if (tid < 64) {
        g_part[which][batch][tid]      = sm[tid] + sm[tid + 64] + sm[tid + 128] + sm[tid + 192];
        g_part[which][batch][tid + 64] = qm[tid] + qm[tid + 64] + qm[tid + 128] + qm[tid + 192];
    }
}
__global__ void k_stats_p2(const float* __restrict__ w, const float* __restrict__ bb, int which) {
    const int c = threadIdx.x;
    float s = 0.f, q = 0.f;
    for (int b2 = 0; b2 < BP; b2++) { s += g_part[which][b2][c]; q += g_part[which][b2][c + 64]; }
    const float mu  = s / (float)NTOT;
    const float var = q / (float)NTOT - mu * mu;
    const float a   = w[c] * rsqrtf(var + 1e-5f);
    g_coef[which][0][c] = a;
    g_coef[which][1][c] = bb[c] - mu * a;
}

// ---------------- K2: z1 = nf@(th0*a)^T + c0 ; w1 = nf@(th1*a)^T + c1 --------
__global__ void __launch_bounds__(256) k_pre(const float* __restrict__ th0w,
                                             const float* __restrict__ th1w) {
    extern __shared__ float sp[];
    float* nf_s = sp;                 // 64*68
    float* W_s  = sp + 4352;          // 128*68
    float* cbuf = sp + 13056;         // 128
    const int tile = blockIdx.x, batch = blockIdx.y, tid = threadIdx.x;

    for (int e = tid; e < 1024; e += 256) {     // nf tile: 64 rows x 16 chunks
        const int row = e >> 4, c4 = e & 15;
        cp16(sptr(nf_s + row * 68 + c4 * 4),
             g_nf + ((size_t)batch * N1 + tile * 64 + row) * 64 + c4 * 4);
    }
    for (int e = tid; e < 2048; e += 256) {     // theta: 128 rows x 16 chunks
        const int wr = e >> 4, wc = e & 15;
        const float* src = (wr < 64) ? (th0w + wr * 64) : (th1w + (wr - 64) * 64);
        cp16(sptr(W_s + wr * 68 + wc * 4), src + wc * 4);
    }
    CP_COMMIT; CP_WAIT0;
    __syncthreads();
    if (tid < 128) {   // c vectors from RAW theta
        float c = 0.f;
        for (int f = 0; f < 64; f++) c += W_s[tid * 68 + f] * g_coef[0][1][f];
        cbuf[tid] = c;
    }
    __syncthreads();
    for (int e = tid; e < 128 * 64; e += 256) {
        const int n = e >> 6, f = e & 63;
        W_s[n * 68 + f] = tfr(W_s[n * 68 + f] * g_coef[0][0][f]);
    }
    __syncthreads();

    const int w = tid >> 5, lane = tid & 31;
    const int band = w >> 1, colg = w & 1;
    const int lq = lane >> 2, lr = lane & 3;
    float acc[8][4];
#pragma unroll
    for (int t = 0; t < 8; t++) { acc[t][0] = acc[t][1] = acc[t][2] = acc[t][3] = 0.f; }
    const int r0 = band * 16;
#pragma unroll
    for (int ks = 0; ks < 8; ks++) {
        const int k0 = ks * 8;
        unsigned a0, a1, a2, a3; ldsm4(a0, a1, a2, a3, nf_s, r0, k0, 68);
#pragma unroll
        for (int tt = 0; tt < 4; tt++) {
            unsigned q0, q1, q2, q3; ldsm4(q0, q1, q2, q3, W_s, colg * 64 + tt * 16, k0, 68);
            mma_tf32(acc[tt * 2],     a0, a1, a2, a3, q0, q2);
            mma_tf32(acc[tt * 2 + 1], a0, a1, a2, a3, q1, q3);
        }
    }
    const size_t rbase = (size_t)batch * N1 + tile * 64 + r0 + lq;
#pragma unroll
    for (int t = 0; t < 8; t++) {
        const int n = colg * 64 + t * 8 + lr * 2;   // 0..127
        const float c0 = cbuf[n], c1 = cbuf[n + 1];
        if (colg == 0) {
            *(float2*)(g_z1 + rbase * 64 + n) =
                make_float2(acc[t][0] + c0, acc[t][1] + c1);
            *(float2*)(g_z1 + (rbase + 8) * 64 + n) =
                make_float2(acc[t][2] + c0, acc[t][3] + c1);
        } else {
            const int nn = n - 64;
            *(float2*)(g_w1 + rbase * 64 + nn) =
                make_float2(tfr(acc[t][0] + c0), tfr(acc[t][1] + c1));
            *(float2*)(g_w1 + (rbase + 8) * 64 + nn) =
                make_float2(tfr(acc[t][2] + c0), tfr(acc[t][3] + c1));
        }
    }
}

// ---------------- K3: adj (softmax+eye+mask) and t = z1 + adj@w1 ------------
__global__ void __launch_bounds__(512) k_adj() {
    extern __shared__ float sa[];
    float* nf_s  = sa;            // later reused as w1_s
    float* adj_s = sa + 34816;
    float* redm  = sa + 51328;
    float* reds  = sa + 51584;
    const int tile = blockIdx.x, batch = blockIdx.y, tid = threadIdx.x;

    const float* nfg = g_nf + (size_t)batch * N1 * 64;
    for (int e = tid; e < 8192; e += 512)
        cp16(sptr(nf_s + (e >> 4) * 68 + (e & 15) * 4), nfg + e * 4);
    CP_COMMIT; CP_WAIT0;
    __syncthreads();

    const int w = tid >> 5, lane = tid & 31;
    const int band = w >> 3, colg = w & 7;
    const int lq = lane >> 2, lr = lane & 3;
    const int rl0 = band * 16 + lq;
    const int rg0 = tile * 32 + rl0, rg1 = rg0 + 8;

    // ---- scores ----
    float acc[8][4];
#pragma unroll
    for (int t = 0; t < 8; t++) { acc[t][0] = acc[t][1] = acc[t][2] = acc[t][3] = 0.f; }
#pragma unroll
    for (int ks = 0; ks < 8; ks++) {
        const int k0 = ks * 8;
        unsigned a0, a1, a2, a3; ldsm4(a0, a1, a2, a3, nf_s, tile * 32 + band * 16, k0, 68);
#pragma unroll
        for (int tt = 0; tt < 4; tt++) {
            unsigned q0, q1, q2, q3; ldsm4(q0, q1, q2, q3, nf_s, colg * 64 + tt * 16, k0, 68);
            mma_tf32(acc[tt * 2],     a0, a1, a2, a3, q0, q2);
            mma_tf32(acc[tt * 2 + 1], a0, a1, a2, a3, q1, q3);
        }
    }

    // ---- diag mask + leaky + max ----
    float m0 = -1e30f, m1 = -1e30f;
#pragma unroll
    for (int t = 0; t < 8; t++) {
#pragma unroll
        for (int j = 0; j < 2; j++) {
            const int col = colg * 64 + t * 8 + lr * 2 + j;
            float v = acc[t][j];
            if (col == rg0) v -= 1e8f;
            v = v > 0.f ? v : SLOPE * v;
            acc[t][j] = v; m0 = fmaxf(m0, v);
            float u = acc[t][2 + j];
            if (col == rg1) u -= 1e8f;
            u = u > 0.f ? u : SLOPE * u;
            acc[t][2 + j] = u; m1 = fmaxf(m1, u);
        }
    }
    m0 = fmaxf(m0, __shfl_xor_sync(~0u, m0, 1)); m0 = fmaxf(m0, __shfl_xor_sync(~0u, m0, 2));
    m1 = fmaxf(m1, __shfl_xor_sync(~0u, m1, 1)); m1 = fmaxf(m1, __shfl_xor_sync(~0u, m1, 2));
    if (lr == 0) { redm[rl0 * 8 + colg] = m0; redm[(rl0 + 8) * 8 + colg] = m1; }
    __syncthreads();

    // prefetch w1 into nf_s region (scores done reading it)
    const float* w1g = g_w1 + (size_t)batch * N1 * 64;
    for (int e = tid; e < 8192; e += 512)
        cp16(sptr(nf_s + (e >> 4) * 68 + (e & 15) * 4), w1g + e * 4);
    CP_COMMIT;

    m0 = -1e30f; m1 = -1e30f;
#pragma unroll
    for (int c = 0; c < 8; c++) {
        m0 = fmaxf(m0, redm[rl0 * 8 + c]);
        m1 = fmaxf(m1, redm[(rl0 + 8) * 8 + c]);
    }
    float s0 = 0.f, s1 = 0.f;
#pragma unroll
    for (int t = 0; t < 8; t++) {
#pragma unroll
        for (int j = 0; j < 2; j++) {
            float e0 = __expf(acc[t][j] - m0);     acc[t][j] = e0;     s0 += e0;
            float e1 = __expf(acc[t][2 + j] - m1); acc[t][2 + j] = e1; s1 += e1;
        }
    }
    s0 += __shfl_xor_sync(~0u, s0, 1); s0 += __shfl_xor_sync(~0u, s0, 2);
    s1 += __shfl_xor_sync(~0u, s1, 1); s1 += __shfl_xor_sync(~0u, s1, 2);
    if (lr == 0) { reds[rl0 * 8 + colg] = s0; reds[(rl0 + 8) * 8 + colg] = s1; }
    __syncthreads();
    float t0 = 0.f, t1 = 0.f;
#pragma unroll
    for (int c = 0; c < 8; c++) { t0 += reds[rl0 * 8 + c]; t1 += reds[(rl0 + 8) * 8 + c]; }
    const float inv0 = 1.f / t0, inv1 = 1.f / t1;
    const float msk = ((tile >= 8) != (colg >= 4)) ? 0.7f : 1.0f;

    // ---- normalize + eye + mask -> adj_s (tf32) ----
#pragma unroll
    for (int t = 0; t < 8; t++) {
#pragma unroll
        for (int j = 0; j < 2; j++) {
            const int col = colg * 64 + t * 8 + lr * 2 + j;
            float v = acc[t][j] * inv0;     if (col == rg0) v += 1.f;
            adj_s[rl0 * 516 + col] = tfr(v * msk);
            float u = acc[t][2 + j] * inv1; if (col == rg1) u += 1.f;
            adj_s[(rl0 + 8) * 516 + col] = tfr(u * msk);
        }
    }
    CP_WAIT0;
    __syncthreads();

    // ---- adj tile -> global (coalesced) ----
    {
        const size_t gb = ((size_t)batch * N1 + tile * 32) * N1;
        for (int e = tid; e < 32 * 128; e += 512) {
            const int r = e >> 7, c = e & 127;
            *(float4*)(g_adj + gb + (size_t)r * N1 + c * 4) = *(float4*)(adj_s + r * 516 + c * 4);
        }
    }

    // ---- v1 = adj @ w1 ; t = z1 + v1 ----
    const int n0 = colg * 8;
    float va[4] = {0.f, 0.f, 0.f, 0.f}, vb[4] = {0.f, 0.f, 0.f, 0.f};
#pragma unroll 4
    for (int ks = 0; ks < 64; ks += 2) {
        int k0 = ks * 8;
        unsigned a0, a1, a2, a3; ldsm4(a0, a1, a2, a3, adj_s, band * 16, k0, 516);
        unsigned b0 = bits(nf_s[(k0 + lr) * 68 + n0 + lq]);
        unsigned b1 = bits(nf_s[(k0 + 4 + lr) * 68 + n0 + lq]);
        mma_tf32(va, a0, a1, a2, a3, b0, b1);
        k0 += 8;
        unsigned c0, c1, c2, c3; ldsm4(c0, c1, c2, c3, adj_s, band * 16, k0, 516);
        unsigned d0 = bits(nf_s[(k0 + lr) * 68 + n0 + lq]);
        unsigned d1 = bits(nf_s[(k0 + 4 + lr) * 68 + n0 + lq]);
        mma_tf32(vb, c0, c1, c2, c3, d0, d1);
    }
    const size_t rb = (size_t)batch * N1 + tile * 32 + band * 16 + lq;
    const int cA = n0 + lr * 2;
    float2 z0 = *(const float2*)(g_z1 + rb * 64 + cA);
    float2 z1 = *(const float2*)(g_z1 + (rb + 8) * 64 + cA);
    *(float2*)(g_t + rb * 64 + cA) =
        make_float2(tfr(va[0] + vb[0] + z0.x), tfr(va[1] + vb[1] + z0.y));
    *(float2*)(g_t + (rb + 8) * 64 + cA) =
        make_float2(tfr(va[2] + vb[2] + z1.x), tfr(va[3] + vb[3] + z1.y));
}

// ---------------- K4: op = adj @ t + (th0b+th1b) -----------------------------
__global__ void __launch_bounds__(512) k_out(const float* __restrict__ th0b,
                                             const float* __restrict__ th1b) {
    extern __shared__ float so[];
    float* t_s = so;               // 34816
    float* cbA = so + 34816;       // 4224
    float* cbB = so + 39040;       // 4224
    const int tile = blockIdx.x, batch = blockIdx.y, tid = threadIdx.x;

    const float* tg = g_t + (size_t)batch * N1 * 64;
    const float* ag = g_adj + ((size_t)batch * N1 + tile * 32) * N1;
    for (int e = tid; e < 8192; e += 512)
        cp16(sptr(t_s + (e >> 4) * 68 + (e & 15) * 4), tg + e * 4);
    for (int e = tid; e < 1024; e += 512) {
        const int r = e >> 5, c = e & 31;
        cp16(sptr(cbA + r * 132 + c * 4), ag + (size_t)r * N1 + c * 4);
    }
    CP_COMMIT;

    const int w = tid >> 5, lane = tid & 31;
    const int band = w >> 3, colg = w & 7;
    const int lq = lane >> 2, lr = lane & 3;
    const int n0 = colg * 8;
    float va[4] = {0.f, 0.f, 0.f, 0.f}, vb[4] = {0.f, 0.f, 0.f, 0.f};

    for (int ch = 0; ch < 4; ch++) {
        float* cb = (ch & 1) ? cbB : cbA;
        if (ch < 3) {
            float* nb = (ch & 1) ? cbA : cbB;
            for (int e = tid; e < 1024; e += 512) {
                const int r = e >> 5, c = e & 31;
                cp16(sptr(nb + r * 132 + c * 4), ag + (size_t)r * N1 + (ch + 1) * 128 + c * 4);
            }
            CP_COMMIT; CP_WAIT1;
        } else {
            CP_WAIT0;
        }
        __syncthreads();
#pragma unroll 4
        for (int ks = 0; ks < 16; ks += 2) {
            int k0 = ks * 8;
            unsigned a0, a1, a2, a3; ldsm4(a0, a1, a2, a3, cb, band * 16, k0, 132);
            unsigned b0 = bits(t_s[(ch * 128 + k0 + lr) * 68 + n0 + lq]);
            unsigned b1 = bits(t_s[(ch * 128 + k0 + 4 + lr) * 68 + n0 + lq]);
            mma_tf32(va, a0, a1, a2, a3, b0, b1);
            k0 += 8;
            unsigned c0, c1, c2, c3; ldsm4(c0, c1, c2, c3, cb, band * 16, k0, 132);
            unsigned d0 = bits(t_s[(ch * 128 + k0 + lr) * 68 + n0 + lq]);
            unsigned d1 = bits(t_s[(ch * 128 + k0 + 4 + lr) * 68 + n0 + lq]);
            mma_tf32(vb, c0, c1, c2, c3, d0, d1);
        }
        __syncthreads();
    }
    const size_t rb = (size_t)batch * N1 + tile * 32 + band * 16 + lq;
    const int cA = n0 + lr * 2;
    const float bc0 = __ldg(th0b + cA) + __ldg(th1b + cA);
    const float bc1 = __ldg(th0b + cA + 1) + __ldg(th1b + cA + 1);
    *(float2*)(g_op + rb * 64 + cA) =
        make_float2(va[0] + vb[0] + bc0, va[1] + vb[1] + bc1);
    *(float2*)(g_op + (rb + 8) * 64 + cA) =
        make_float2(va[2] + vb[2] + bc0, va[3] + vb[3] + bc1);
}

// ---------------- K5: BN1 affine + leaky + mean pool -------------------------
__global__ void k_final(float* __restrict__ out) {
    const int idx = blockIdx.x * 256 + threadIdx.x;
    const int c = idx & 63;
    const int n = (idx >> 6) & 255;
    const int b = idx >> 14;
    const float a = g_coef[1][0][c], d = g_coef[1][1][c];
    float s = 0.f;
#pragma unroll 2
    for (int l = 0; l < LWIN; l++)
#pragma unroll
        for (int m = 0; m < 2; m++) {
            float v = g_op[(((size_t)(b * LWIN + l)) * N1 + m * NNODE + n) * 64 + c];
            v = a * v + d;
            s += (v > 0.f) ? v : SLOPE * v;
        }
    out[idx] = s * (1.f / 32.f);
}

// ---------------- launch ------------------------------------------------------
extern "C" void kernel_launch(void* const* d_in, const int* in_sizes, int n_in,
                              void* d_out, int out_size) {
    const float* x    = (const float*)d_in[0];
    const float* w2   = (const float*)d_in[1];
    const float* b2   = (const float*)d_in[2];
    const float* bn0w = (const float*)d_in[3];
    const float* bn0b = (const float*)d_in[4];
    const float* th0w = (const float*)d_in[5];
    const float* th0b = (const float*)d_in[6];
    const float* th1w = (const float*)d_in[7];
    const float* th1b = (const float*)d_in[8];
    const float* bn1w = (const float*)d_in[9];
    const float* bn1b = (const float*)d_in[10];
    float* out = (float*)d_out;

    const int SMEM_PRE = 13184 * 4;   // 52736
    const int SMEM_ADJ = 51840 * 4;   // 207360
    const int SMEM_OUT = 43264 * 4;   // 173056
    cudaFuncSetAttribute(k_pre, cudaFuncAttributeMaxDynamicSharedMemorySize, SMEM_PRE);
    cudaFuncSetAttribute(k_adj, cudaFuncAttributeMaxDynamicSharedMemorySize, SMEM_ADJ);
    cudaFuncSetAttribute(k_out, cudaFuncAttributeMaxDynamicSharedMemorySize, SMEM_OUT);

    k_nf<<<dim3(8, BP), 256>>>(x, w2, b2);
    k_stats_p1<<<BP, 256>>>(0);
    k_stats_p2<<<1, 64>>>(bn0w, bn0b, 0);
    k_pre<<<dim3(8, BP), 256, SMEM_PRE>>>(th0w, th1w);
    k_adj<<<dim3(16, BP), 512, SMEM_ADJ>>>();
    k_out<<<dim3(16, BP), 512, SMEM_OUT>>>(th0b, th1b);
    k_stats_p1<<<BP, 256>>>(1);
    k_stats_p2<<<1, 64>>>(bn1w, bn1b, 1);
    k_final<<<1024, 256>>>(out);
}

// round 5
// speedup vs baseline: 8.6965x; 2.1585x over previous
#include <cuda_runtime.h>
#include <cuda_fp16.h>
#include <math.h>
#include <stdint.h>

#define BATCH   16
#define SEQ     17
#define NNODE   256
#define FDIM    64
#define LWIN    16
#define BP      256         // BATCH*LWIN
#define N1      512
#define OUTD    64
#define NTOT    (BP*N1)
#define SLOPE   0.01f

// ---------------- scratch ----------------------------------------------------
__device__ __half g_nfh [(size_t)BP*N1*FDIM];   // 16.7 MB
__device__ __half g_w1h [(size_t)BP*N1*FDIM];   // 16.7 MB
__device__ __half g_adjh[(size_t)BP*N1*N1];     // 134 MB
__device__ __half g_th  [(size_t)BP*N1*FDIM];   // 16.7 MB
__device__ float  g_z1  [(size_t)BP*N1*FDIM];   // 33.5 MB (exact)
__device__ float  g_op  [(size_t)BP*N1*OUTD];   // 33.5 MB (exact)
__device__ float  g_part[2][BP][128];
__device__ float  g_coef[2][2][64];

// ---------------- helpers ----------------------------------------------------
__device__ __forceinline__ uint32_t sptr(const void* p) {
    return (uint32_t)__cvta_generic_to_shared(p);
}
__device__ __forceinline__ void cp16(uint32_t d, const void* s) {
    asm volatile("cp.async.cg.shared.global [%0],[%1],16;" :: "r"(d), "l"(s));
}
#define CP_COMMIT asm volatile("cp.async.commit_group;")
#define CP_WAIT0  asm volatile("cp.async.wait_group 0;")
#define CP_WAIT1  asm volatile("cp.async.wait_group 1;")

__device__ __forceinline__ void mma_f16(float c[4], unsigned a0, unsigned a1,
                                        unsigned a2, unsigned a3,
                                        unsigned b0, unsigned b1) {
    asm volatile(
        "mma.sync.aligned.m16n8k16.row.col.f32.f16.f16.f32 "
        "{%0,%1,%2,%3},{%4,%5,%6,%7},{%8,%9},{%0,%1,%2,%3};"
        : "+f"(c[0]), "+f"(c[1]), "+f"(c[2]), "+f"(c[3])
        : "r"(a0), "r"(a1), "r"(a2), "r"(a3), "r"(b0), "r"(b1));
}
// A-fragment (16x16 halves, row-major): regs a0..a3
__device__ __forceinline__ void ldsm4h(unsigned& r0, unsigned& r1, unsigned& r2, unsigned& r3,
                                       const __half* base, int row0, int k0, int stride) {
    const int lane = threadIdx.x & 31;
    uint32_t a = sptr(base + (row0 + (lane & 15)) * stride + k0 + ((lane >> 4) << 3));
    asm volatile("ldmatrix.sync.aligned.m8n8.x4.shared.b16 {%0,%1,%2,%3},[%4];"
                 : "=r"(r0), "=r"(r1), "=r"(r2), "=r"(r3) : "r"(a));
}
// B-fragment from [n][k] storage (k contiguous): plain x2
__device__ __forceinline__ void ldsm2h_n(unsigned& r0, unsigned& r1,
                                         const __half* base, int n0, int k0, int stride) {
    const int l4 = threadIdx.x & 15;
    uint32_t a = sptr(base + (n0 + (l4 & 7)) * stride + k0 + ((l4 >> 3) << 3));
    asm volatile("ldmatrix.sync.aligned.m8n8.x2.shared.b16 {%0,%1},[%2];"
                 : "=r"(r0), "=r"(r1) : "r"(a));
}
// B-fragment from [k][n] storage (n contiguous): x2.trans
__device__ __forceinline__ void ldsm2h_t(unsigned& r0, unsigned& r1,
                                         const __half* base, int k0, int n0, int stride) {
    const int l4 = threadIdx.x & 15;
    uint32_t a = sptr(base + (k0 + l4) * stride + n0);
    asm volatile("ldmatrix.sync.aligned.m8n8.x2.trans.shared.b16 {%0,%1},[%2];"
                 : "=r"(r0), "=r"(r1) : "r"(a));
}

// ---------------- K1: nf = gather(X) @ w2^T + b2  (fp16 MMA) ----------------
__global__ void __launch_bounds__(256) k_nf(const float* __restrict__ x,
                                            const float* __restrict__ w2,
                                            const float* __restrict__ b2) {
    __shared__ __half xh[64 * 72];
    __shared__ __half wh[64 * 72];
    const int tile = blockIdx.x, batch = blockIdx.y, tid = threadIdx.x;
    const int b = batch / LWIN, l = batch % LWIN;

    for (int e = tid; e < 1024; e += 256) {      // 64 rows x 16 float4 chunks
        const int row = e >> 4, c4 = e & 15;
        const int r = tile * 64 + row, m = r >> 8, n = r & 255;
        float4 xv = *(const float4*)(x + ((size_t)(b * SEQ + l + m) * NNODE + n) * FDIM + c4 * 4);
        *(__half2*)(xh + row * 72 + c4 * 4)     = __floats2half2_rn(xv.x, xv.y);
        *(__half2*)(xh + row * 72 + c4 * 4 + 2) = __floats2half2_rn(xv.z, xv.w);
        float4 wv = *(const float4*)(w2 + row * 64 + c4 * 4);
        *(__half2*)(wh + row * 72 + c4 * 4)     = __floats2half2_rn(wv.x, wv.y);
        *(__half2*)(wh + row * 72 + c4 * 4 + 2) = __floats2half2_rn(wv.z, wv.w);
    }
    __syncthreads();

    const int w = tid >> 5, lane = tid & 31;
    const int band = w >> 1, colg = w & 1;
    const int lq = lane >> 2, lr = lane & 3;
    float acc[4][4];
#pragma unroll
    for (int t = 0; t < 4; t++) { acc[t][0] = acc[t][1] = acc[t][2] = acc[t][3] = 0.f; }
#pragma unroll
    for (int ks = 0; ks < 4; ks++) {
        const int k0 = ks * 16;
        unsigned a0, a1, a2, a3; ldsm4h(a0, a1, a2, a3, xh, band * 16, k0, 72);
#pragma unroll
        for (int t = 0; t < 4; t++) {
            unsigned b0, b1; ldsm2h_n(b0, b1, wh, colg * 32 + t * 8, k0, 72);
            mma_f16(acc[t], a0, a1, a2, a3, b0, b1);
        }
    }
    const size_t ob = ((size_t)batch * N1 + tile * 64 + band * 16 + lq) * 64;
#pragma unroll
    for (int t = 0; t < 4; t++) {
        const int c = colg * 32 + t * 8 + lr * 2;
        const float bb0 = __ldg(b2 + c), bb1 = __ldg(b2 + c + 1);
        *(__half2*)(g_nfh + ob + c) = __floats2half2_rn(acc[t][0] + bb0, acc[t][1] + bb1);
        *(__half2*)(g_nfh + ob + (size_t)8 * 64 + c) = __floats2half2_rn(acc[t][2] + bb0, acc[t][3] + bb1);
    }
}

// ---------------- BN stats ---------------------------------------------------
__global__ void k_stats_p1(int which) {
    const int batch = blockIdx.x, tid = threadIdx.x;
    const int c = tid & 63, rg = tid >> 6;
    float s = 0.f, q = 0.f;
    if (which == 0) {
        const __half* p = g_nfh + (size_t)batch * N1 * 64;
        for (int r = rg * 128; r < rg * 128 + 128; r++) {
            float v = __half2float(p[(size_t)r * 64 + c]);
            s += v; q += v * v;
        }
    } else {
        const float* p = g_op + (size_t)batch * N1 * 64;
        for (int r = rg * 128; r < rg * 128 + 128; r++) {
            float v = p[(size_t)r * 64 + c];
            s += v; q += v * v;
        }
    }
    __shared__ float sm[256], qm[256];
    sm[tid] = s; qm[tid] = q;
    __syncthreads();
    if (tid < 64) {
        g_part[which][batch][tid]      = sm[tid] + sm[tid + 64] + sm[tid + 128] + sm[tid + 192];
        g_part[which][batch][tid + 64] = qm[tid] + qm[tid + 64] + qm[tid + 128] + qm[tid + 192];
    }
}
__global__ void k_stats_p2(const float* __restrict__ w, const float* __restrict__ bb, int which) {
    const int c = threadIdx.x;
    float s = 0.f, q = 0.f;
    for (int b2 = 0; b2 < BP; b2++) { s += g_part[which][b2][c]; q += g_part[which][b2][c + 64]; }
    const float mu  = s / (float)NTOT;
    const float var = q / (float)NTOT - mu * mu;
    const float a   = w[c] * rsqrtf(var + 1e-5f);
    g_coef[which][0][c] = a;
    g_coef[which][1][c] = bb[c] - mu * a;
}

// ---------------- K2: z1 = xb@th0^T ; w1 = xb@th1^T (affine-folded) ---------
// smem bytes: Wf[128*68]f @0 | cbuf[128]f @34816 | nfh[64*72]h @35328 | Wh[128*72]h @44544
__global__ void __launch_bounds__(256) k_pre(const float* __restrict__ th0w,
                                             const float* __restrict__ th1w) {
    extern __shared__ char sraw[];
    float*  Wf   = (float*)sraw;
    float*  cbuf = (float*)(sraw + 34816);
    __half* nfh  = (__half*)(sraw + 35328);
    __half* Wh   = (__half*)(sraw + 44544);
    const int tile = blockIdx.x, batch = blockIdx.y, tid = threadIdx.x;

    for (int e = tid; e < 512; e += 256) {       // nf tile: 64 rows x 8 chunks (half)
        const int row = e >> 3, c8 = e & 7;
        cp16(sptr(nfh + row * 72 + c8 * 8),
             g_nfh + ((size_t)batch * N1 + tile * 64 + row) * 64 + c8 * 8);
    }
    for (int e = tid; e < 2048; e += 256) {      // theta fp32: 128 rows x 16 chunks
        const int wr = e >> 4, wc = e & 15;
        const float* src = (wr < 64) ? (th0w + wr * 64) : (th1w + (wr - 64) * 64);
        cp16(sptr(Wf + wr * 68 + wc * 4), src + wc * 4);
    }
    CP_COMMIT; CP_WAIT0;
    __syncthreads();
    if (tid < 128) {
        float c = 0.f;
        for (int f = 0; f < 64; f++) c += Wf[tid * 68 + f] * g_coef[0][1][f];
        cbuf[tid] = c;
    }
    __syncthreads();
    for (int e = tid; e < 128 * 64; e += 256) {
        const int n = e >> 6, f = e & 63;
        Wh[n * 72 + f] = __float2half(Wf[n * 68 + f] * g_coef[0][0][f]);
    }
    __syncthreads();

    const int w = tid >> 5, lane = tid & 31;
    const int band = w >> 1, colg = w & 1;
    const int lq = lane >> 2, lr = lane & 3;
    float acc[8][4];
#pragma unroll
    for (int t = 0; t < 8; t++) { acc[t][0] = acc[t][1] = acc[t][2] = acc[t][3] = 0.f; }
#pragma unroll
    for (int ks = 0; ks < 4; ks++) {
        const int k0 = ks * 16;
        unsigned a0, a1, a2, a3; ldsm4h(a0, a1, a2, a3, nfh, band * 16, k0, 72);
#pragma unroll
        for (int t = 0; t < 8; t++) {
            unsigned b0, b1; ldsm2h_n(b0, b1, Wh, colg * 64 + t * 8, k0, 72);
            mma_f16(acc[t], a0, a1, a2, a3, b0, b1);
        }
    }
    const size_t rbase = (size_t)batch * N1 + tile * 64 + band * 16 + lq;
#pragma unroll
    for (int t = 0; t < 8; t++) {
        const int n = colg * 64 + t * 8 + lr * 2;
        const float c0 = cbuf[n], c1 = cbuf[n + 1];
        if (colg == 0) {
            *(float2*)(g_z1 + rbase * 64 + n) = make_float2(acc[t][0] + c0, acc[t][1] + c1);
            *(float2*)(g_z1 + (rbase + 8) * 64 + n) = make_float2(acc[t][2] + c0, acc[t][3] + c1);
        } else {
            const int nn = n - 64;
            *(__half2*)(g_w1h + rbase * 64 + nn) = __floats2half2_rn(acc[t][0] + c0, acc[t][1] + c1);
            *(__half2*)(g_w1h + (rbase + 8) * 64 + nn) = __floats2half2_rn(acc[t][2] + c0, acc[t][3] + c1);
        }
    }
}

// ---------------- K3: adj (softmax+eye+mask) and t = z1 + adj@w1 ------------
// smem bytes: nf_s[512*72]h @0 | adj_s[32*520]h @73728 | redm @107008 | reds @108032
__global__ void __launch_bounds__(512, 2) k_adj() {
    extern __shared__ char sraw[];
    __half* nf_s  = (__half*)sraw;            // reused as w1 buffer
    __half* adj_s = (__half*)(sraw + 73728);
    float*  redm  = (float*)(sraw + 107008);
    float*  reds  = (float*)(sraw + 108032);
    const int tile = blockIdx.x, batch = blockIdx.y, tid = threadIdx.x;

    const __half* nfg = g_nfh + (size_t)batch * N1 * 64;
    for (int e = tid; e < 4096; e += 512)
        cp16(sptr(nf_s + (e >> 3) * 72 + (e & 7) * 8), nfg + e * 8);
    CP_COMMIT; CP_WAIT0;
    __syncthreads();

    const int w = tid >> 5, lane = tid & 31;
    const int band = w >> 3, colg = w & 7;
    const int lq = lane >> 2, lr = lane & 3;
    const int rl0 = band * 16 + lq;
    const int rg0 = tile * 32 + rl0, rg1 = rg0 + 8;

    // ---- scores: 32 rows x 512 cols ----
    float acc[8][4];
#pragma unroll
    for (int t = 0; t < 8; t++) { acc[t][0] = acc[t][1] = acc[t][2] = acc[t][3] = 0.f; }
#pragma unroll
    for (int ks = 0; ks < 4; ks++) {
        const int k0 = ks * 16;
        unsigned a0, a1, a2, a3; ldsm4h(a0, a1, a2, a3, nf_s, tile * 32 + band * 16, k0, 72);
#pragma unroll
        for (int t = 0; t < 8; t++) {
            unsigned b0, b1; ldsm2h_n(b0, b1, nf_s, colg * 64 + t * 8, k0, 72);
            mma_f16(acc[t], a0, a1, a2, a3, b0, b1);
        }
    }

    // ---- diag mask + leaky + max ----
    float m0 = -1e30f, m1 = -1e30f;
#pragma unroll
    for (int t = 0; t < 8; t++) {
#pragma unroll
        for (int j = 0; j < 2; j++) {
            const int col = colg * 64 + t * 8 + lr * 2 + j;
            float v = acc[t][j];
            if (col == rg0) v -= 1e8f;
            v = v > 0.f ? v : SLOPE * v;
            acc[t][j] = v; m0 = fmaxf(m0, v);
            float u = acc[t][2 + j];
            if (col == rg1) u -= 1e8f;
            u = u > 0.f ? u : SLOPE * u;
            acc[t][2 + j] = u; m1 = fmaxf(m1, u);
        }
    }
    m0 = fmaxf(m0, __shfl_xor_sync(~0u, m0, 1)); m0 = fmaxf(m0, __shfl_xor_sync(~0u, m0, 2));
    m1 = fmaxf(m1, __shfl_xor_sync(~0u, m1, 1)); m1 = fmaxf(m1, __shfl_xor_sync(~0u, m1, 2));
    if (lr == 0) { redm[rl0 * 8 + colg] = m0; redm[(rl0 + 8) * 8 + colg] = m1; }
    __syncthreads();

    // prefetch w1 into nf_s (scores done with it)
    const __half* w1g = g_w1h + (size_t)batch * N1 * 64;
    for (int e = tid; e < 4096; e += 512)
        cp16(sptr(nf_s + (e >> 3) * 72 + (e & 7) * 8), w1g + e * 8);
    CP_COMMIT;

    m0 = -1e30f; m1 = -1e30f;
#pragma unroll
    for (int c = 0; c < 8; c++) {
        m0 = fmaxf(m0, redm[rl0 * 8 + c]);
        m1 = fmaxf(m1, redm[(rl0 + 8) * 8 + c]);
    }
    float s0 = 0.f, s1 = 0.f;
#pragma unroll
    for (int t = 0; t < 8; t++) {
#pragma unroll
        for (int j = 0; j < 2; j++) {
            float e0 = __expf(acc[t][j] - m0);     acc[t][j] = e0;     s0 += e0;
            float e1 = __expf(acc[t][2 + j] - m1); acc[t][2 + j] = e1; s1 += e1;
        }
    }
    s0 += __shfl_xor_sync(~0u, s0, 1); s0 += __shfl_xor_sync(~0u, s0, 2);
    s1 += __shfl_xor_sync(~0u, s1, 1); s1 += __shfl_xor_sync(~0u, s1, 2);
    if (lr == 0) { reds[rl0 * 8 + colg] = s0; reds[(rl0 + 8) * 8 + colg] = s1; }
    __syncthreads();
    float t0 = 0.f, t1 = 0.f;
#pragma unroll
    for (int c = 0; c < 8; c++) { t0 += reds[rl0 * 8 + c]; t1 += reds[(rl0 + 8) * 8 + c]; }
    const float inv0 = 1.f / t0, inv1 = 1.f / t1;
    const float msk = ((tile >= 8) != (colg >= 4)) ? 0.7f : 1.0f;

    // ---- normalize + eye + mask -> adj_s (half) ----
#pragma unroll
    for (int t = 0; t < 8; t++) {
#pragma unroll
        for (int j = 0; j < 2; j++) {
            const int col = colg * 64 + t * 8 + lr * 2 + j;
            float v = acc[t][j] * inv0;     if (col == rg0) v += 1.f;
            adj_s[rl0 * 520 + col] = __float2half(v * msk);
            float u = acc[t][2 + j] * inv1; if (col == rg1) u += 1.f;
            adj_s[(rl0 + 8) * 520 + col] = __float2half(u * msk);
        }
    }
    CP_WAIT0;
    __syncthreads();

    // ---- adj tile -> global (half, coalesced) ----
    {
        const size_t gb = ((size_t)batch * N1 + tile * 32) * N1;
        for (int e = tid; e < 2048; e += 512) {
            const int r = e >> 6, c8 = e & 63;
            *(uint4*)(g_adjh + gb + (size_t)r * N1 + c8 * 8) =
                *(const uint4*)(adj_s + r * 520 + c8 * 8);
        }
    }

    // ---- v1 = adj @ w1 ; t = z1 + v1 ----
    const int n0 = colg * 8;
    float va[4] = {0.f, 0.f, 0.f, 0.f}, vb[4] = {0.f, 0.f, 0.f, 0.f};
#pragma unroll 4
    for (int ks = 0; ks < 32; ks += 2) {
        int k0 = ks * 16;
        unsigned a0, a1, a2, a3; ldsm4h(a0, a1, a2, a3, adj_s, band * 16, k0, 520);
        unsigned b0, b1; ldsm2h_t(b0, b1, nf_s, k0, n0, 72);
        mma_f16(va, a0, a1, a2, a3, b0, b1);
        k0 += 16;
        unsigned c0, c1, c2, c3; ldsm4h(c0, c1, c2, c3, adj_s, band * 16, k0, 520);
        unsigned d0, d1; ldsm2h_t(d0, d1, nf_s, k0, n0, 72);
        mma_f16(vb, c0, c1, c2, c3, d0, d1);
    }
    const size_t rb = (size_t)batch * N1 + tile * 32 + band * 16 + lq;
    const int cA = n0 + lr * 2;
    float2 z0 = *(const float2*)(g_z1 + rb * 64 + cA);
    float2 z1v = *(const float2*)(g_z1 + (rb + 8) * 64 + cA);
    *(__half2*)(g_th + rb * 64 + cA) =
        __floats2half2_rn(va[0] + vb[0] + z0.x, va[1] + vb[1] + z0.y);
    *(__half2*)(g_th + (rb + 8) * 64 + cA) =
        __floats2half2_rn(va[2] + vb[2] + z1v.x, va[3] + vb[3] + z1v.y);
}

// ---------------- K4: op = adj @ t + (th0b+th1b) -----------------------------
// smem bytes: t_s[512*72]h @0 | cbA[32*136]h @73728 | cbB @82432
__global__ void __launch_bounds__(512, 2) k_out(const float* __restrict__ th0b,
                                                const float* __restrict__ th1b) {
    extern __shared__ char sraw[];
    __half* t_s = (__half*)sraw;
    __half* cbA = (__half*)(sraw + 73728);
    __half* cbB = (__half*)(sraw + 82432);
    const int tile = blockIdx.x, batch = blockIdx.y, tid = threadIdx.x;

    const __half* tg = g_th + (size_t)batch * N1 * 64;
    const __half* ag = g_adjh + ((size_t)batch * N1 + tile * 32) * N1;
    for (int e = tid; e < 4096; e += 512)
        cp16(sptr(t_s + (e >> 3) * 72 + (e & 7) * 8), tg + e * 8);
    for (int e = tid; e < 512; e += 512) {
        const int r = e >> 4, c8 = e & 15;
        cp16(sptr(cbA + r * 136 + c8 * 8), ag + (size_t)r * N1 + c8 * 8);
    }
    CP_COMMIT;

    const int w = tid >> 5, lane = tid & 31;
    const int band = w >> 3, colg = w & 7;
    const int lq = lane >> 2, lr = lane & 3;
    const int n0 = colg * 8;
    float va[4] = {0.f, 0.f, 0.f, 0.f}, vb[4] = {0.f, 0.f, 0.f, 0.f};

    for (int ch = 0; ch < 4; ch++) {
        __half* cb = (ch & 1) ? cbB : cbA;
        if (ch < 3) {
            __half* nb = (ch & 1) ? cbA : cbB;
            for (int e = tid; e < 512; e += 512) {
                const int r = e >> 4, c8 = e & 15;
                cp16(sptr(nb + r * 136 + c8 * 8), ag + (size_t)r * N1 + (ch + 1) * 128 + c8 * 8);
            }
            CP_COMMIT; CP_WAIT1;
        } else {
            CP_WAIT0;
        }
        __syncthreads();
#pragma unroll 4
        for (int ks = 0; ks < 8; ks += 2) {
            int k0 = ks * 16;
            unsigned a0, a1, a2, a3; ldsm4h(a0, a1, a2, a3, cb, band * 16, k0, 136);
            unsigned b0, b1; ldsm2h_t(b0, b1, t_s, ch * 128 + k0, n0, 72);
            mma_f16(va, a0, a1, a2, a3, b0, b1);
            k0 += 16;
            unsigned c0, c1, c2, c3; ldsm4h(c0, c1, c2, c3, cb, band * 16, k0, 136);
            unsigned d0, d1; ldsm2h_t(d0, d1, t_s, ch * 128 + k0, n0, 72);
            mma_f16(vb, c0, c1, c2, c3, d0, d1);
        }
        __syncthreads();
    }
    const size_t rb = (size_t)batch * N1 + tile * 32 + band * 16 + lq;
    const int cA = n0 + lr * 2;
    const float bc0 = __ldg(th0b + cA) + __ldg(th1b + cA);
    const float bc1 = __ldg(th0b + cA + 1) + __ldg(th1b + cA + 1);
    *(float2*)(g_op + rb * 64 + cA) = make_float2(va[0] + vb[0] + bc0, va[1] + vb[1] + bc1);
    *(float2*)(g_op + (rb + 8) * 64 + cA) = make_float2(va[2] + vb[2] + bc0, va[3] + vb[3] + bc1);
}

// ---------------- K5: BN1 affine + leaky + mean pool -------------------------
__global__ void k_final(float* __restrict__ out) {
    const int idx = blockIdx.x * 256 + threadIdx.x;
    const int c = idx & 63;
    const int n = (idx >> 6) & 255;
    const int b = idx >> 14;
    const float a = g_coef[1][0][c], d = g_coef[1][1][c];
    float s = 0.f;
#pragma unroll 2
    for (int l = 0; l < LWIN; l++)
#pragma unroll
        for (int m = 0; m < 2; m++) {
            float v = g_op[(((size_t)(b * LWIN + l)) * N1 + m * NNODE + n) * 64 + c];
            v = a * v + d;
            s += (v > 0.f) ? v : SLOPE * v;
        }
    out[idx] = s * (1.f / 32.f);
}

// ---------------- launch ------------------------------------------------------
extern "C" void kernel_launch(void* const* d_in, const int* in_sizes, int n_in,
                              void* d_out, int out_size) {
    const float* x    = (const float*)d_in[0];
    const float* w2   = (const float*)d_in[1];
    const float* b2   = (const float*)d_in[2];
    const float* bn0w = (const float*)d_in[3];
    const float* bn0b = (const float*)d_in[4];
    const float* th0w = (const float*)d_in[5];
    const float* th0b = (const float*)d_in[6];
    const float* th1w = (const float*)d_in[7];
    const float* th1b = (const float*)d_in[8];
    const float* bn1w = (const float*)d_in[9];
    const float* bn1b = (const float*)d_in[10];
    float* out = (float*)d_out;

    const int SMEM_PRE = 62976;
    const int SMEM_ADJ = 109056;
    const int SMEM_OUT = 91136;
    cudaFuncSetAttribute(k_pre, cudaFuncAttributeMaxDynamicSharedMemorySize, SMEM_PRE);
    cudaFuncSetAttribute(k_adj, cudaFuncAttributeMaxDynamicSharedMemorySize, SMEM_ADJ);
    cudaFuncSetAttribute(k_out, cudaFuncAttributeMaxDynamicSharedMemorySize, SMEM_OUT);

    k_nf<<<dim3(8, BP), 256>>>(x, w2, b2);
    k_stats_p1<<<BP, 256>>>(0);
    k_stats_p2<<<1, 64>>>(bn0w, bn0b, 0);
    k_pre<<<dim3(8, BP), 256, SMEM_PRE>>>(th0w, th1w);
    k_adj<<<dim3(16, BP), 512, SMEM_ADJ>>>();
    k_out<<<dim3(16, BP), 512, SMEM_OUT>>>(th0b, th1b);
    k_stats_p1<<<BP, 256>>>(1);
    k_stats_p2<<<1, 64>>>(bn1w, bn1b, 1);
    k_final<<<1024, 256>>>(out);
}

// round 6
// speedup vs baseline: 9.4313x; 1.0845x over previous
#include <cuda_runtime.h>
#include <cuda_fp16.h>
#include <math.h>
#include <stdint.h>

#define BATCH   16
#define SEQ     17
#define NNODE   256
#define FDIM    64
#define LWIN    16
#define BP      256         // BATCH*LWIN
#define N1      512
#define OUTD    64
#define NTOT    (BP*N1)
#define SLOPE   0.01f

// ---------------- scratch ----------------------------------------------------
__device__ __half g_nfh [(size_t)BP*N1*FDIM];
__device__ __half g_w1h [(size_t)BP*N1*FDIM];
__device__ __half g_adjh[(size_t)BP*N1*N1];     // 134 MB
__device__ __half g_th  [(size_t)BP*N1*FDIM];
__device__ float  g_z1  [(size_t)BP*N1*FDIM];
__device__ float  g_op  [(size_t)BP*N1*OUTD];
__device__ float  g_part[2][BP][128];
__device__ float  g_coef[2][2][64];
__device__ __half g_Wh  [128*64];               // theta (th0;th1) * a, half
__device__ float  g_cbuf[128];                  // theta @ d

// ---------------- helpers ----------------------------------------------------
__device__ __forceinline__ uint32_t sptr(const void* p) {
    return (uint32_t)__cvta_generic_to_shared(p);
}
__device__ __forceinline__ void cp16(uint32_t d, const void* s) {
    asm volatile("cp.async.cg.shared.global [%0],[%1],16;" :: "r"(d), "l"(s));
}
#define CP_COMMIT asm volatile("cp.async.commit_group;")
#define CP_WAIT0  asm volatile("cp.async.wait_group 0;")
#define CP_WAIT1  asm volatile("cp.async.wait_group 1;")

__device__ __forceinline__ void mma_f16(float c[4], unsigned a0, unsigned a1,
                                        unsigned a2, unsigned a3,
                                        unsigned b0, unsigned b1) {
    asm volatile(
        "mma.sync.aligned.m16n8k16.row.col.f32.f16.f16.f32 "
        "{%0,%1,%2,%3},{%4,%5,%6,%7},{%8,%9},{%0,%1,%2,%3};"
        : "+f"(c[0]), "+f"(c[1]), "+f"(c[2]), "+f"(c[3])
        : "r"(a0), "r"(a1), "r"(a2), "r"(a3), "r"(b0), "r"(b1));
}
__device__ __forceinline__ void ldsm4h(unsigned& r0, unsigned& r1, unsigned& r2, unsigned& r3,
                                       const __half* base, int row0, int k0, int stride) {
    const int lane = threadIdx.x & 31;
    uint32_t a = sptr(base + (row0 + (lane & 15)) * stride + k0 + ((lane >> 4) << 3));
    asm volatile("ldmatrix.sync.aligned.m8n8.x4.shared.b16 {%0,%1,%2,%3},[%4];"
                 : "=r"(r0), "=r"(r1), "=r"(r2), "=r"(r3) : "r"(a));
}
__device__ __forceinline__ void ldsm2h_n(unsigned& r0, unsigned& r1,
                                         const __half* base, int n0, int k0, int stride) {
    const int l4 = threadIdx.x & 15;
    uint32_t a = sptr(base + (n0 + (l4 & 7)) * stride + k0 + ((l4 >> 3) << 3));
    asm volatile("ldmatrix.sync.aligned.m8n8.x2.shared.b16 {%0,%1},[%2];"
                 : "=r"(r0), "=r"(r1) : "r"(a));
}
__device__ __forceinline__ void ldsm2h_t(unsigned& r0, unsigned& r1,
                                         const __half* base, int k0, int n0, int stride) {
    const int l4 = threadIdx.x & 15;
    uint32_t a = sptr(base + (k0 + l4) * stride + n0);
    asm volatile("ldmatrix.sync.aligned.m8n8.x2.trans.shared.b16 {%0,%1},[%2];"
                 : "=r"(r0), "=r"(r1) : "r"(a));
}

// ---------------- K1: nf = gather(X) @ w2^T + b2 ----------------------------
__global__ void __launch_bounds__(256) k_nf(const float* __restrict__ x,
                                            const float* __restrict__ w2,
                                            const float* __restrict__ b2) {
    __shared__ __half xh[64 * 72];
    __shared__ __half wh[64 * 72];
    const int tile = blockIdx.x, batch = blockIdx.y, tid = threadIdx.x;
    const int b = batch / LWIN, l = batch % LWIN;

    for (int e = tid; e < 1024; e += 256) {
        const int row = e >> 4, c4 = e & 15;
        const int r = tile * 64 + row, m = r >> 8, n = r & 255;
        float4 xv = *(const float4*)(x + ((size_t)(b * SEQ + l + m) * NNODE + n) * FDIM + c4 * 4);
        *(__half2*)(xh + row * 72 + c4 * 4)     = __floats2half2_rn(xv.x, xv.y);
        *(__half2*)(xh + row * 72 + c4 * 4 + 2) = __floats2half2_rn(xv.z, xv.w);
        float4 wv = *(const float4*)(w2 + row * 64 + c4 * 4);
        *(__half2*)(wh + row * 72 + c4 * 4)     = __floats2half2_rn(wv.x, wv.y);
        *(__half2*)(wh + row * 72 + c4 * 4 + 2) = __floats2half2_rn(wv.z, wv.w);
    }
    __syncthreads();

    const int w = tid >> 5, lane = tid & 31;
    const int band = w >> 1, colg = w & 1;
    const int lq = lane >> 2, lr = lane & 3;
    float acc[4][4];
#pragma unroll
    for (int t = 0; t < 4; t++) { acc[t][0] = acc[t][1] = acc[t][2] = acc[t][3] = 0.f; }
#pragma unroll
    for (int ks = 0; ks < 4; ks++) {
        const int k0 = ks * 16;
        unsigned a0, a1, a2, a3; ldsm4h(a0, a1, a2, a3, xh, band * 16, k0, 72);
#pragma unroll
        for (int t = 0; t < 4; t++) {
            unsigned b0, b1; ldsm2h_n(b0, b1, wh, colg * 32 + t * 8, k0, 72);
            mma_f16(acc[t], a0, a1, a2, a3, b0, b1);
        }
    }
    const size_t ob = ((size_t)batch * N1 + tile * 64 + band * 16 + lq) * 64;
#pragma unroll
    for (int t = 0; t < 4; t++) {
        const int c = colg * 32 + t * 8 + lr * 2;
        const float bb0 = __ldg(b2 + c), bb1 = __ldg(b2 + c + 1);
        *(__half2*)(g_nfh + ob + c) = __floats2half2_rn(acc[t][0] + bb0, acc[t][1] + bb1);
        *(__half2*)(g_nfh + ob + (size_t)8 * 64 + c) = __floats2half2_rn(acc[t][2] + bb0, acc[t][3] + bb1);
    }
}

// ---------------- BN stats ---------------------------------------------------
__global__ void k_stats_p1(int which) {
    const int batch = blockIdx.x, tid = threadIdx.x;
    const int c = tid & 63, rg = tid >> 6;
    float s = 0.f, q = 0.f;
    if (which == 0) {
        const __half* p = g_nfh + (size_t)batch * N1 * 64;
        for (int r = rg * 128; r < rg * 128 + 128; r++) {
            float v = __half2float(p[(size_t)r * 64 + c]);
            s += v; q += v * v;
        }
    } else {
        const float* p = g_op + (size_t)batch * N1 * 64;
        for (int r = rg * 128; r < rg * 128 + 128; r++) {
            float v = p[(size_t)r * 64 + c];
            s += v; q += v * v;
        }
    }
    __shared__ float sm[256], qm[256];
    sm[tid] = s; qm[tid] = q;
    __syncthreads();
    if (tid < 64) {
        g_part[which][batch][tid]      = sm[tid] + sm[tid + 64] + sm[tid + 128] + sm[tid + 192];
        g_part[which][batch][tid + 64] = qm[tid] + qm[tid + 64] + qm[tid + 128] + qm[tid + 192];
    }
}
__global__ void k_stats_p2(const float* __restrict__ w, const float* __restrict__ bb, int which) {
    const int c = threadIdx.x;
    float s = 0.f, q = 0.f;
    for (int b2 = 0; b2 < BP; b2++) { s += g_part[which][b2][c]; q += g_part[which][b2][c + 64]; }
    const float mu  = s / (float)NTOT;
    const float var = q / (float)NTOT - mu * mu;
    const float a   = w[c] * rsqrtf(var + 1e-5f);
    g_coef[which][0][c] = a;
    g_coef[which][1][c] = bb[c] - mu * a;
}

// ---------------- K1b: one-time theta fold (Wh = theta*a, cbuf = theta@d) ---
__global__ void k_prep(const float* __restrict__ th0w, const float* __restrict__ th1w) {
    const int n = threadIdx.x;                 // 0..127
    const float* wr = (n < 64) ? (th0w + n * 64) : (th1w + (n - 64) * 64);
    float c = 0.f;
    for (int k = 0; k < 64; k++) {
        const float wv = wr[k];
        c += wv * g_coef[0][1][k];
        g_Wh[n * 64 + k] = __float2half(wv * g_coef[0][0][k]);
    }
    g_cbuf[n] = c;
}

// ---------------- K2: z1 = xb@th0^T ; w1 = xb@th1^T (prefolded) -------------
// smem bytes: nfh[64*72]h @0 | Wh[128*72]h @9216 | cbuf[128]f @27648
__global__ void __launch_bounds__(256) k_pre() {
    extern __shared__ char sraw[];
    __half* nfh  = (__half*)sraw;
    __half* Wh   = (__half*)(sraw + 9216);
    float*  cbuf = (float*)(sraw + 27648);
    const int tile = blockIdx.x, batch = blockIdx.y, tid = threadIdx.x;

    for (int e = tid; e < 512; e += 256) {
        const int row = e >> 3, c8 = e & 7;
        cp16(sptr(nfh + row * 72 + c8 * 8),
             g_nfh + ((size_t)batch * N1 + tile * 64 + row) * 64 + c8 * 8);
    }
    for (int e = tid; e < 1024; e += 256) {
        const int row = e >> 3, c8 = e & 7;
        cp16(sptr(Wh + row * 72 + c8 * 8), g_Wh + row * 64 + c8 * 8);
    }
    if (tid < 32) cp16(sptr(cbuf + tid * 4), g_cbuf + tid * 4);
    CP_COMMIT; CP_WAIT0;
    __syncthreads();

    const int w = tid >> 5, lane = tid & 31;
    const int band = w >> 1, colg = w & 1;
    const int lq = lane >> 2, lr = lane & 3;
    float acc[8][4];
#pragma unroll
    for (int t = 0; t < 8; t++) { acc[t][0] = acc[t][1] = acc[t][2] = acc[t][3] = 0.f; }
#pragma unroll
    for (int ks = 0; ks < 4; ks++) {
        const int k0 = ks * 16;
        unsigned a0, a1, a2, a3; ldsm4h(a0, a1, a2, a3, nfh, band * 16, k0, 72);
#pragma unroll
        for (int t = 0; t < 8; t++) {
            unsigned b0, b1; ldsm2h_n(b0, b1, Wh, colg * 64 + t * 8, k0, 72);
            mma_f16(acc[t], a0, a1, a2, a3, b0, b1);
        }
    }
    const size_t rbase = (size_t)batch * N1 + tile * 64 + band * 16 + lq;
#pragma unroll
    for (int t = 0; t < 8; t++) {
        const int n = colg * 64 + t * 8 + lr * 2;
        const float c0 = cbuf[n], c1 = cbuf[n + 1];
        if (colg == 0) {
            *(float2*)(g_z1 + rbase * 64 + n) = make_float2(acc[t][0] + c0, acc[t][1] + c1);
            *(float2*)(g_z1 + (rbase + 8) * 64 + n) = make_float2(acc[t][2] + c0, acc[t][3] + c1);
        } else {
            const int nn = n - 64;
            *(__half2*)(g_w1h + rbase * 64 + nn) = __floats2half2_rn(acc[t][0] + c0, acc[t][1] + c1);
            *(__half2*)(g_w1h + (rbase + 8) * 64 + nn) = __floats2half2_rn(acc[t][2] + c0, acc[t][3] + c1);
        }
    }
}

// ---------------- K3: adj (softmax, no-max) and t = z1 + adj@w1 -------------
// smem bytes: nf_s[512*72]h @0 | adj_s[32*520]h @73728 | reds[32*8]f @107008
__global__ void __launch_bounds__(512, 2) k_adj() {
    extern __shared__ char sraw[];
    __half* nf_s  = (__half*)sraw;            // reused as w1 buffer
    __half* adj_s = (__half*)(sraw + 73728);
    float*  reds  = (float*)(sraw + 107008);
    const int tile = blockIdx.x, batch = blockIdx.y, tid = threadIdx.x;

    const __half* nfg = g_nfh + (size_t)batch * N1 * 64;
    for (int e = tid; e < 4096; e += 512)
        cp16(sptr(nf_s + (e >> 3) * 72 + (e & 7) * 8), nfg + e * 8);
    CP_COMMIT; CP_WAIT0;
    __syncthreads();

    const int w = tid >> 5, lane = tid & 31;
    const int band = w >> 3, colg = w & 7;
    const int lq = lane >> 2, lr = lane & 3;
    const int rl0 = band * 16 + lq;
    const int rg0 = tile * 32 + rl0, rg1 = rg0 + 8;

    // ---- scores: 32 rows x 512 cols ----
    float acc[8][4];
#pragma unroll
    for (int t = 0; t < 8; t++) { acc[t][0] = acc[t][1] = acc[t][2] = acc[t][3] = 0.f; }
#pragma unroll
    for (int ks = 0; ks < 4; ks++) {
        const int k0 = ks * 16;
        unsigned a0, a1, a2, a3; ldsm4h(a0, a1, a2, a3, nf_s, tile * 32 + band * 16, k0, 72);
#pragma unroll
        for (int t = 0; t < 8; t++) {
            unsigned b0, b1; ldsm2h_n(b0, b1, nf_s, colg * 64 + t * 8, k0, 72);
            mma_f16(acc[t], a0, a1, a2, a3, b0, b1);
        }
    }
    __syncthreads();   // all warps done reading nf_s

    // prefetch w1 into nf_s while doing softmax
    const __half* w1g = g_w1h + (size_t)batch * N1 * 64;
    for (int e = tid; e < 4096; e += 512)
        cp16(sptr(nf_s + (e >> 3) * 72 + (e & 7) * 8), w1g + e * 8);
    CP_COMMIT;

    // ---- leaky + exp (no max subtraction; diag underflows to exactly 0) ----
    float s0 = 0.f, s1 = 0.f;
#pragma unroll
    for (int t = 0; t < 8; t++) {
#pragma unroll
        for (int j = 0; j < 2; j++) {
            const int col = colg * 64 + t * 8 + lr * 2 + j;
            float v = acc[t][j];
            if (col == rg0) v -= 1e8f;
            v = v > 0.f ? v : SLOPE * v;
            float e0 = __expf(v); acc[t][j] = e0; s0 += e0;
            float u = acc[t][2 + j];
            if (col == rg1) u -= 1e8f;
            u = u > 0.f ? u : SLOPE * u;
            float e1 = __expf(u); acc[t][2 + j] = e1; s1 += e1;
        }
    }
    s0 += __shfl_xor_sync(~0u, s0, 1); s0 += __shfl_xor_sync(~0u, s0, 2);
    s1 += __shfl_xor_sync(~0u, s1, 1); s1 += __shfl_xor_sync(~0u, s1, 2);
    if (lr == 0) { reds[rl0 * 8 + colg] = s0; reds[(rl0 + 8) * 8 + colg] = s1; }
    __syncthreads();
    float t0 = 0.f, t1 = 0.f;
#pragma unroll
    for (int c = 0; c < 8; c++) { t0 += reds[rl0 * 8 + c]; t1 += reds[(rl0 + 8) * 8 + c]; }
    const float inv0 = 1.f / t0, inv1 = 1.f / t1;
    const float msk = ((tile >= 8) != (colg >= 4)) ? 0.7f : 1.0f;

    // ---- normalize + eye + mask -> adj_s ----
#pragma unroll
    for (int t = 0; t < 8; t++) {
#pragma unroll
        for (int j = 0; j < 2; j++) {
            const int col = colg * 64 + t * 8 + lr * 2 + j;
            float v = acc[t][j] * inv0;     if (col == rg0) v += 1.f;
            adj_s[rl0 * 520 + col] = __float2half(v * msk);
            float u = acc[t][2 + j] * inv1; if (col == rg1) u += 1.f;
            adj_s[(rl0 + 8) * 520 + col] = __float2half(u * msk);
        }
    }
    CP_WAIT0;
    __syncthreads();

    // ---- adj tile -> global ----
    {
        const size_t gb = ((size_t)batch * N1 + tile * 32) * N1;
        for (int e = tid; e < 2048; e += 512) {
            const int r = e >> 6, c8 = e & 63;
            *(uint4*)(g_adjh + gb + (size_t)r * N1 + c8 * 8) =
                *(const uint4*)(adj_s + r * 520 + c8 * 8);
        }
    }

    // ---- v1 = adj @ w1 ; t = z1 + v1 ----
    const int n0 = colg * 8;
    float va[4] = {0.f, 0.f, 0.f, 0.f}, vb[4] = {0.f, 0.f, 0.f, 0.f};
#pragma unroll 4
    for (int ks = 0; ks < 32; ks += 2) {
        int k0 = ks * 16;
        unsigned a0, a1, a2, a3; ldsm4h(a0, a1, a2, a3, adj_s, band * 16, k0, 520);
        unsigned b0, b1; ldsm2h_t(b0, b1, nf_s, k0, n0, 72);
        mma_f16(va, a0, a1, a2, a3, b0, b1);
        k0 += 16;
        unsigned c0, c1, c2, c3; ldsm4h(c0, c1, c2, c3, adj_s, band * 16, k0, 520);
        unsigned d0, d1; ldsm2h_t(d0, d1, nf_s, k0, n0, 72);
        mma_f16(vb, c0, c1, c2, c3, d0, d1);
    }
    const size_t rb = (size_t)batch * N1 + tile * 32 + band * 16 + lq;
    const int cA = n0 + lr * 2;
    float2 z0 = *(const float2*)(g_z1 + rb * 64 + cA);
    float2 z1v = *(const float2*)(g_z1 + (rb + 8) * 64 + cA);
    *(__half2*)(g_th + rb * 64 + cA) =
        __floats2half2_rn(va[0] + vb[0] + z0.x, va[1] + vb[1] + z0.y);
    *(__half2*)(g_th + (rb + 8) * 64 + cA) =
        __floats2half2_rn(va[2] + vb[2] + z1v.x, va[3] + vb[3] + z1v.y);
}

// ---------------- K4: op = adj @ t + (th0b+th1b), 64-row tiles --------------
// smem bytes: t_s[512*72]h @0 | cbA[64*136]h @73728 | cbB @91136
__global__ void __launch_bounds__(512, 2) k_out(const float* __restrict__ th0b,
                                                const float* __restrict__ th1b) {
    extern __shared__ char sraw[];
    __half* t_s = (__half*)sraw;
    __half* cbA = (__half*)(sraw + 73728);
    __half* cbB = (__half*)(sraw + 91136);
    const int tile = blockIdx.x, batch = blockIdx.y, tid = threadIdx.x;

    const __half* tg = g_th + (size_t)batch * N1 * 64;
    const __half* ag = g_adjh + ((size_t)batch * N1 + tile * 64) * N1;
    for (int e = tid; e < 4096; e += 512)
        cp16(sptr(t_s + (e >> 3) * 72 + (e & 7) * 8), tg + e * 8);
    for (int e = tid; e < 1024; e += 512) {
        const int r = e >> 4, c8 = e & 15;
        cp16(sptr(cbA + r * 136 + c8 * 8), ag + (size_t)r * N1 + c8 * 8);
    }
    CP_COMMIT;

    const int w = tid >> 5, lane = tid & 31;
    const int band = w >> 2, colg = w & 3;           // 4 row-bands x 4 col-groups
    const int lq = lane >> 2, lr = lane & 3;
    float acc[2][4];
#pragma unroll
    for (int t = 0; t < 2; t++) { acc[t][0] = acc[t][1] = acc[t][2] = acc[t][3] = 0.f; }

    for (int ch = 0; ch < 4; ch++) {
        __half* cb = (ch & 1) ? cbB : cbA;
        if (ch < 3) {
            __half* nb = (ch & 1) ? cbA : cbB;
            for (int e = tid; e < 1024; e += 512) {
                const int r = e >> 4, c8 = e & 15;
                cp16(sptr(nb + r * 136 + c8 * 8), ag + (size_t)r * N1 + (ch + 1) * 128 + c8 * 8);
            }
            CP_COMMIT; CP_WAIT1;
        } else {
            CP_WAIT0;
        }
        __syncthreads();
#pragma unroll
        for (int ks = 0; ks < 8; ks++) {
            const int k0 = ks * 16;
            unsigned a0, a1, a2, a3; ldsm4h(a0, a1, a2, a3, cb, band * 16, k0, 136);
#pragma unroll
            for (int nt = 0; nt < 2; nt++) {
                unsigned b0, b1; ldsm2h_t(b0, b1, t_s, ch * 128 + k0, colg * 16 + nt * 8, 72);
                mma_f16(acc[nt], a0, a1, a2, a3, b0, b1);
            }
        }
        __syncthreads();
    }
    const size_t rb = (size_t)batch * N1 + tile * 64 + band * 16 + lq;
#pragma unroll
    for (int nt = 0; nt < 2; nt++) {
        const int cA = colg * 16 + nt * 8 + lr * 2;
        const float bc0 = __ldg(th0b + cA) + __ldg(th1b + cA);
        const float bc1 = __ldg(th0b + cA + 1) + __ldg(th1b + cA + 1);
        *(float2*)(g_op + rb * 64 + cA) = make_float2(acc[nt][0] + bc0, acc[nt][1] + bc1);
        *(float2*)(g_op + (rb + 8) * 64 + cA) = make_float2(acc[nt][2] + bc0, acc[nt][3] + bc1);
    }
}

// ---------------- K5: BN1 affine + leaky + mean pool -------------------------
__global__ void k_final(float* __restrict__ out) {
    const int idx = blockIdx.x * 256 + threadIdx.x;
    const int c = idx & 63;
    const int n = (idx >> 6) & 255;
    const int b = idx >> 14;
    const float a = g_coef[1][0][c], d = g_coef[1][1][c];
    float s = 0.f;
#pragma unroll 2
    for (int l = 0; l < LWIN; l++)
#pragma unroll
        for (int m = 0; m < 2; m++) {
            float v = g_op[(((size_t)(b * LWIN + l)) * N1 + m * NNODE + n) * 64 + c];
            v = a * v + d;
            s += (v > 0.f) ? v : SLOPE * v;
        }
    out[idx] = s * (1.f / 32.f);
}

// ---------------- launch ------------------------------------------------------
extern "C" void kernel_launch(void* const* d_in, const int* in_sizes, int n_in,
                              void* d_out, int out_size) {
    const float* x    = (const float*)d_in[0];
    const float* w2   = (const float*)d_in[1];
    const float* b2   = (const float*)d_in[2];
    const float* bn0w = (const float*)d_in[3];
    const float* bn0b = (const float*)d_in[4];
    const float* th0w = (const float*)d_in[5];
    const float* th0b = (const float*)d_in[6];
    const float* th1w = (const float*)d_in[7];
    const float* th1b = (const float*)d_in[8];
    const float* bn1w = (const float*)d_in[9];
    const float* bn1b = (const float*)d_in[10];
    float* out = (float*)d_out;

    const int SMEM_PRE = 28160;
    const int SMEM_ADJ = 108032;
    const int SMEM_OUT = 108544;
    cudaFuncSetAttribute(k_pre, cudaFuncAttributeMaxDynamicSharedMemorySize, SMEM_PRE);
    cudaFuncSetAttribute(k_adj, cudaFuncAttributeMaxDynamicSharedMemorySize, SMEM_ADJ);
    cudaFuncSetAttribute(k_out, cudaFuncAttributeMaxDynamicSharedMemorySize, SMEM_OUT);

    k_nf<<<dim3(8, BP), 256>>>(x, w2, b2);
    k_stats_p1<<<BP, 256>>>(0);
    k_stats_p2<<<1, 64>>>(bn0w, bn0b, 0);
    k_prep<<<1, 128>>>(th0w, th1w);
    k_pre<<<dim3(8, BP), 256, SMEM_PRE>>>();
    k_adj<<<dim3(16, BP), 512, SMEM_ADJ>>>();
    k_out<<<dim3(8, BP), 512, SMEM_OUT>>>(th0b, th1b);
    k_stats_p1<<<BP, 256>>>(1);
    k_stats_p2<<<1, 64>>>(bn1w, bn1b, 1);
    k_final<<<1024, 256>>>(out);
}